// round 2
// baseline (speedup 1.0000x reference)
#include <cuda_runtime.h>
#include <math.h>
#include <stdint.h>

// ---------------- problem constants ----------------
#define CB   2
#define CS   4096
#define CH   12
#define CD   64
#define CW   256
#define CDM  768
#define CDFF 3072
#define CNB  16          // S / W
#define CLW  769         // 3W + 1 (band + global column), logical width
#define CLP  772         // padded row stride (multiple of 4 for float4 alignment)
#define CL   2
#define CNEG (-1000000000.0f)
#define CSCALE 0.125f    // 1/sqrt(64)

#define MROWS (CB*CS)    // 8192

// ---------------- scratch (allocation-free rule: __device__ globals) --------
__device__ float g_x   [MROWS*CDM];
__device__ float g_q   [MROWS*CDM];
__device__ float g_k   [MROWS*CDM];
__device__ float g_v   [MROWS*CDM];
__device__ float g_attn[MROWS*CDM];
__device__ float g_h1  [MROWS*CDFF];
__device__ float g_sc  [(size_t)CB*CH*CS*CLP];   // padded stride 772
__device__ float g_qg  [CB*CDM];

// ---------------- helpers ----------------
__device__ __forceinline__ float gelu_tanh(float x) {
    float x3 = x * x * x;
    return 0.5f * x * (1.0f + tanhf(0.7978845608028654f * (x + 0.044715f * x3)));
}

__device__ __forceinline__ float block_reduce_sum256(float v, float* red) {
    int tid = threadIdx.x;
    red[tid] = v; __syncthreads();
    #pragma unroll
    for (int o = 128; o > 0; o >>= 1) {
        if (tid < o) red[tid] += red[tid + o];
        __syncthreads();
    }
    float r = red[0]; __syncthreads();
    return r;
}

// ---------------- fused embed + LayerNorm ----------------
__global__ void embed_ln_kernel(const int* __restrict__ ids,
                                const float* __restrict__ we,
                                const float* __restrict__ pe,
                                const float* __restrict__ gam,
                                const float* __restrict__ bet,
                                float* __restrict__ x) {
    __shared__ float red[256];
    int row = blockIdx.x;          // b*S + s
    int s = row % CS;
    int id = ids[row];
    int tid = threadIdx.x;
    const float* wp = we + (size_t)id * CDM;
    const float* pp = pe + (size_t)s * CDM;
    float e[3];
    float sm = 0.f;
    #pragma unroll
    for (int i = 0; i < 3; i++) {
        int d = tid + i * 256;
        e[i] = wp[d] + pp[d];
        sm += e[i];
    }
    float mean = block_reduce_sum256(sm, red) * (1.0f / CDM);
    float vs = 0.f;
    #pragma unroll
    for (int i = 0; i < 3; i++) { float t = e[i] - mean; vs += t * t; }
    float var = block_reduce_sum256(vs, red) * (1.0f / CDM);
    float inv = rsqrtf(var + 1e-5f);
    float* xr = x + (size_t)row * CDM;
    #pragma unroll
    for (int i = 0; i < 3; i++) {
        int d = tid + i * 256;
        xr[d] = (e[i] - mean) * inv * gam[d] + bet[d];
    }
}

// ---------------- residual add + LayerNorm (in place on x) ----------------
__global__ void add_ln_kernel(float* __restrict__ x,
                              const float* __restrict__ y,
                              const float* __restrict__ gam,
                              const float* __restrict__ bet) {
    __shared__ float red[256];
    int row = blockIdx.x;
    int tid = threadIdx.x;
    float* xr = x + (size_t)row * CDM;
    const float* yr = y + (size_t)row * CDM;
    float e[3];
    float sm = 0.f;
    #pragma unroll
    for (int i = 0; i < 3; i++) {
        int d = tid + i * 256;
        e[i] = xr[d] + yr[d];
        sm += e[i];
    }
    float mean = block_reduce_sum256(sm, red) * (1.0f / CDM);
    float vs = 0.f;
    #pragma unroll
    for (int i = 0; i < 3; i++) { float t = e[i] - mean; vs += t * t; }
    float var = block_reduce_sum256(vs, red) * (1.0f / CDM);
    float inv = rsqrtf(var + 1e-5f);
    #pragma unroll
    for (int i = 0; i < 3; i++) {
        int d = tid + i * 256;
        xr[d] = (e[i] - mean) * inv * gam[d] + bet[d];
    }
}

// ---------------- tiled fp32 GEMM: C = A[M,K] * B[K,N] + bias, optional GELU -
// BM=128, BN=128, BK=8, 256 threads, 8x8 per thread. All dims multiples.
template<int ACT>
__global__ __launch_bounds__(256)
void gemm_bias_kernel(const float* __restrict__ A,
                      const float* __restrict__ B,
                      const float* __restrict__ bias,
                      float* __restrict__ C,
                      int M, int N, int K) {
    __shared__ float As[8][128];
    __shared__ float Bs[8][128];
    int tid = threadIdx.x;
    int m0 = blockIdx.y * 128;
    int n0 = blockIdx.x * 128;
    int tx = tid & 15, ty = tid >> 4;

    int arow = tid >> 1;
    int acol = (tid & 1) * 4;
    int brow = tid >> 5;
    int bcol = (tid & 31) * 4;

    float acc[8][8];
    #pragma unroll
    for (int i = 0; i < 8; i++)
        #pragma unroll
        for (int j = 0; j < 8; j++) acc[i][j] = 0.f;

    const float* Ap = A + (size_t)(m0 + arow) * K + acol;
    const float* Bp = B + (size_t)brow * N + n0 + bcol;

    for (int k0 = 0; k0 < K; k0 += 8) {
        float4 av = *(const float4*)(Ap + k0);
        As[acol + 0][arow] = av.x;
        As[acol + 1][arow] = av.y;
        As[acol + 2][arow] = av.z;
        As[acol + 3][arow] = av.w;
        *(float4*)&Bs[brow][bcol] = *(const float4*)(Bp + (size_t)k0 * N);
        __syncthreads();
        #pragma unroll
        for (int kk = 0; kk < 8; kk++) {
            float a[8], b[8];
            *(float4*)(a)     = *(const float4*)&As[kk][ty * 8];
            *(float4*)(a + 4) = *(const float4*)&As[kk][ty * 8 + 4];
            *(float4*)(b)     = *(const float4*)&Bs[kk][tx * 8];
            *(float4*)(b + 4) = *(const float4*)&Bs[kk][tx * 8 + 4];
            #pragma unroll
            for (int i = 0; i < 8; i++)
                #pragma unroll
                for (int j = 0; j < 8; j++)
                    acc[i][j] += a[i] * b[j];
        }
        __syncthreads();
    }

    float bvals[8];
    #pragma unroll
    for (int j = 0; j < 8; j++) bvals[j] = bias[n0 + tx * 8 + j];

    #pragma unroll
    for (int i = 0; i < 8; i++) {
        int row = m0 + ty * 8 + i;
        float4 o0, o1;
        float t[8];
        #pragma unroll
        for (int j = 0; j < 8; j++) {
            float vv = acc[i][j] + bvals[j];
            if (ACT == 1) vv = gelu_tanh(vv);
            t[j] = vv;
        }
        o0 = make_float4(t[0], t[1], t[2], t[3]);
        o1 = make_float4(t[4], t[5], t[6], t[7]);
        *(float4*)&C[(size_t)row * N + n0 + tx * 8]     = o0;
        *(float4*)&C[(size_t)row * N + n0 + tx * 8 + 4] = o1;
    }
}

// ---------------- band scores: per (b,h,n) Q[W,64] x Kwin[3W,64]^T ----------
// grid: (12 ktiles, 4 qtiles, B*H*NB), block 256. 64x64 output tile, depth 64.
__global__ __launch_bounds__(256)
void band_scores_kernel(const float* __restrict__ q,
                        const float* __restrict__ k,
                        const int* __restrict__ am,
                        float* __restrict__ sc) {
    __shared__ float Qs[64][64];   // [d][qi_local]
    __shared__ float Ks[64][64];   // [d][kj_local]
    int z = blockIdx.z;
    int n = z % CNB;
    int h = (z / CNB) % CH;
    int b = z / (CNB * CH);
    int qt = blockIdx.y;           // 0..3
    int kt = blockIdx.x;           // 0..11
    int tid = threadIdx.x;

    int base_s    = n * CW + qt * 64;
    int base_kpos = n * CW - CW + kt * 64;

    #pragma unroll
    for (int i = 0; i < 4; i++) {
        int sid = tid + i * 256;
        int r = sid >> 4, c4 = (sid & 15) << 2;
        float4 v = *(const float4*)&q[((size_t)(b * CS + base_s + r)) * CDM + h * 64 + c4];
        Qs[c4 + 0][r] = v.x * CSCALE;
        Qs[c4 + 1][r] = v.y * CSCALE;
        Qs[c4 + 2][r] = v.z * CSCALE;
        Qs[c4 + 3][r] = v.w * CSCALE;
    }
    #pragma unroll
    for (int i = 0; i < 4; i++) {
        int sid = tid + i * 256;
        int r = sid >> 4, c4 = (sid & 15) << 2;
        int kpos = base_kpos + r;
        float4 v = make_float4(0.f, 0.f, 0.f, 0.f);
        if (kpos >= 0 && kpos < CS)
            v = *(const float4*)&k[((size_t)(b * CS + kpos)) * CDM + h * 64 + c4];
        Ks[c4 + 0][r] = v.x;
        Ks[c4 + 1][r] = v.y;
        Ks[c4 + 2][r] = v.z;
        Ks[c4 + 3][r] = v.w;
    }
    __syncthreads();

    int tx = tid & 15, ty = tid >> 4;
    float acc[4][4];
    #pragma unroll
    for (int i = 0; i < 4; i++)
        #pragma unroll
        for (int j = 0; j < 4; j++) acc[i][j] = 0.f;

    #pragma unroll 8
    for (int kk = 0; kk < 64; kk++) {
        float a[4], bb[4];
        *(float4*)a  = *(const float4*)&Qs[kk][ty * 4];
        *(float4*)bb = *(const float4*)&Ks[kk][tx * 4];
        #pragma unroll
        for (int i = 0; i < 4; i++)
            #pragma unroll
            for (int j = 0; j < 4; j++)
                acc[i][j] += a[i] * bb[j];
    }

    #pragma unroll
    for (int i = 0; i < 4; i++) {
        int qi = qt * 64 + ty * 4 + i;      // 0..255
        int s  = n * CW + qi;
        size_t rowbase = ((size_t)((b * CH + h) * CS + s)) * CLP;
        #pragma unroll
        for (int j = 0; j < 4; j++) {
            int kj = kt * 64 + tx * 4 + j;  // 0..767
            int kpos = n * CW - CW + kj;
            bool ok = (kj >= qi) && (kj <= qi + 2 * CW) &&
                      (kpos >= 0) && (kpos < CS) && (kpos != 0) &&
                      (am[b * CS + kpos] > 0);
            sc[rowbase + kj] = ok ? acc[i][j] : CNEG;
        }
    }
}

// ---------------- global-key column of scores (index 768) -------------------
__global__ void sg_kernel(const float* __restrict__ q,
                          const float* __restrict__ k,
                          const int* __restrict__ am,
                          float* __restrict__ sc) {
    int gw = (blockIdx.x * blockDim.x + threadIdx.x) >> 5;  // row = (b*H+h)*S + s
    int lane = threadIdx.x & 31;
    if (gw >= CB * CH * CS) return;
    int s = gw % CS;
    int h = (gw / CS) % CH;
    int b = gw / (CS * CH);
    float val = CNEG;
    if (am[b * CS] > 0) {
        const float* qp = &q[((size_t)(b * CS + s)) * CDM + h * 64];
        const float* kp = &k[((size_t)(b * CS)) * CDM + h * 64];
        float p = qp[lane] * kp[lane] + qp[lane + 32] * kp[lane + 32];
        #pragma unroll
        for (int o = 16; o > 0; o >>= 1) p += __shfl_xor_sync(0xffffffffu, p, o);
        val = p * CSCALE;
    }
    if (lane == 0) sc[(size_t)gw * CLP + 768] = val;
}

// ---------------- row softmax over 769 entries (stride CLP) ----------------
__global__ void softmax_kernel(float* __restrict__ sc) {
    __shared__ float row[CLW];
    __shared__ float red[128];
    size_t r = blockIdx.x;
    float* p = sc + r * CLP;
    int tid = threadIdx.x;   // 128
    float mx = -1e30f;
    for (int i = tid; i < CLW; i += 128) { row[i] = p[i]; mx = fmaxf(mx, row[i]); }
    red[tid] = mx; __syncthreads();
    #pragma unroll
    for (int o = 64; o > 0; o >>= 1) {
        if (tid < o) red[tid] = fmaxf(red[tid], red[tid + o]);
        __syncthreads();
    }
    mx = red[0]; __syncthreads();
    float sm = 0.f;
    for (int i = tid; i < CLW; i += 128) {
        float e = __expf(row[i] - mx);
        row[i] = e; sm += e;
    }
    red[tid] = sm; __syncthreads();
    #pragma unroll
    for (int o = 64; o > 0; o >>= 1) {
        if (tid < o) red[tid] += red[tid + o];
        __syncthreads();
    }
    float inv = 1.0f / red[0];
    for (int i = tid; i < CLW; i += 128) p[i] = row[i] * inv;
}

// ---------------- AV: out = attn_band @ Vwin + attn_g * v0 ------------------
// grid: (4 qtiles, B*H*NB), block 256. Output 64 queries x 64 dims.
__global__ __launch_bounds__(256)
void av_kernel(const float* __restrict__ sc,
               const float* __restrict__ v,
               float* __restrict__ out) {
    __shared__ float As[64][64];   // [kj][q]
    __shared__ float Vs[64][64];   // [kj][d]
    int z = blockIdx.y;
    int n = z % CNB;
    int h = (z / CNB) % CH;
    int b = z / (CNB * CH);
    int qt = blockIdx.x;
    int tid = threadIdx.x;
    int tx = tid & 15, ty = tid >> 4;

    float acc[4][4];
    #pragma unroll
    for (int i = 0; i < 4; i++)
        #pragma unroll
        for (int j = 0; j < 4; j++) acc[i][j] = 0.f;

    for (int kc = 0; kc < 12; kc++) {
        #pragma unroll
        for (int i = 0; i < 4; i++) {
            int sid = tid + i * 256;
            int r = sid >> 4, c4 = (sid & 15) << 2;
            int s = n * CW + qt * 64 + r;
            float4 a4 = *(const float4*)&sc[((size_t)((b * CH + h) * CS + s)) * CLP + kc * 64 + c4];
            As[c4 + 0][r] = a4.x;
            As[c4 + 1][r] = a4.y;
            As[c4 + 2][r] = a4.z;
            As[c4 + 3][r] = a4.w;
            int kpos = n * CW - CW + kc * 64 + r;
            float4 v4 = make_float4(0.f, 0.f, 0.f, 0.f);
            if (kpos >= 0 && kpos < CS)
                v4 = *(const float4*)&v[((size_t)(b * CS + kpos)) * CDM + h * 64 + c4];
            *(float4*)&Vs[r][c4] = v4;
        }
        __syncthreads();
        #pragma unroll 8
        for (int kk = 0; kk < 64; kk++) {
            float a[4], bb[4];
            *(float4*)a  = *(const float4*)&As[kk][ty * 4];
            *(float4*)bb = *(const float4*)&Vs[kk][tx * 4];
            #pragma unroll
            for (int i = 0; i < 4; i++)
                #pragma unroll
                for (int j = 0; j < 4; j++)
                    acc[i][j] += a[i] * bb[j];
        }
        __syncthreads();
    }

    #pragma unroll
    for (int i = 0; i < 4; i++) {
        int s = n * CW + qt * 64 + ty * 4 + i;
        float g = sc[((size_t)((b * CH + h) * CS + s)) * CLP + 768];
        #pragma unroll
        for (int j = 0; j < 4; j++) {
            int d = tx * 4 + j;
            float v0 = v[((size_t)(b * CS)) * CDM + h * 64 + d];
            out[((size_t)(b * CS + s)) * CDM + h * 64 + d] = acc[i][j] + g * v0;
        }
    }
}

// ---------------- qg = (x[:,0] @ Wqg + bqg) * scale ----------------
__global__ void qg_kernel(const float* __restrict__ x,
                          const float* __restrict__ Wqg,
                          const float* __restrict__ bqg,
                          float* __restrict__ qg) {
    int nidx = blockIdx.x * 256 + threadIdx.x;  // 0..767
    int b = blockIdx.y;
    const float* xr = x + (size_t)(b * CS) * CDM;
    float acc = bqg[nidx];
    for (int kk = 0; kk < CDM; kk++)
        acc += xr[kk] * Wqg[(size_t)kk * CDM + nidx];
    qg[b * CDM + nidx] = acc * CSCALE;
}

// ---------------- global attention for row 0 (overwrites out row 0) ---------
__global__ void global_attn_kernel(const float* __restrict__ qg,
                                   const float* __restrict__ kg,
                                   const float* __restrict__ vg,
                                   const int* __restrict__ am,
                                   float* __restrict__ out) {
    __shared__ float scs[CS];      // 16KB
    __shared__ float red[256];
    __shared__ float qs[64];
    int h = blockIdx.x, b = blockIdx.y;
    int tid = threadIdx.x;        // 256
    if (tid < 64) qs[tid] = qg[b * CDM + h * 64 + tid];
    __syncthreads();

    float mx = -1e30f;
    for (int s = tid; s < CS; s += 256) {
        const float* kp = &kg[((size_t)(b * CS + s)) * CDM + h * 64];
        float dd = 0.f;
        #pragma unroll
        for (int e = 0; e < 64; e++) dd += qs[e] * kp[e];
        if (am[b * CS + s] <= 0) dd = CNEG;
        scs[s] = dd;
        mx = fmaxf(mx, dd);
    }
    red[tid] = mx; __syncthreads();
    #pragma unroll
    for (int o = 128; o > 0; o >>= 1) {
        if (tid < o) red[tid] = fmaxf(red[tid], red[tid + o]);
        __syncthreads();
    }
    mx = red[0]; __syncthreads();

    float sm = 0.f;
    for (int s = tid; s < CS; s += 256) {
        float e = __expf(scs[s] - mx);
        scs[s] = e; sm += e;
    }
    float tot = block_reduce_sum256(sm, red);
    float inv = 1.0f / tot;
    __syncthreads();

    int d = tid & 63, sl = tid >> 6;     // 4 slices of 1024 keys
    float acc = 0.f;
    for (int s = sl * 1024; s < (sl + 1) * 1024; s++)
        acc += scs[s] * vg[((size_t)(b * CS + s)) * CDM + h * 64 + d];
    red[tid] = acc; __syncthreads();
    if (sl == 0) {
        float t = red[d] + red[64 + d] + red[128 + d] + red[192 + d];
        out[((size_t)(b * CS)) * CDM + h * 64 + d] = t * inv;
    }
}

// ---------------- classifier head ----------------
__global__ void cls_kernel(const float* __restrict__ x,
                           const float* __restrict__ Wc,
                           const float* __restrict__ bc,
                           float* __restrict__ out) {
    __shared__ float red[256];
    int b = blockIdx.x >> 1, c = blockIdx.x & 1;
    int tid = threadIdx.x;
    const float* xr = x + (size_t)(b * CS) * CDM;
    float acc = 0.f;
    for (int d = tid; d < CDM; d += 256) acc += xr[d] * Wc[d * 2 + c];
    float tot = block_reduce_sum256(acc, red);
    if (tid == 0) out[b * 2 + c] = tot + bc[c];
}

// ---------------- launch ----------------
extern "C" void kernel_launch(void* const* d_in, const int* in_sizes, int n_in,
                              void* d_out, int out_size) {
    const int*   ids  = (const int*)d_in[0];
    const int*   am   = (const int*)d_in[1];
    const float* we   = (const float*)d_in[2];
    const float* pe   = (const float*)d_in[3];
    const float* lnes = (const float*)d_in[4];
    const float* lneb = (const float*)d_in[5];
    const float* Wq   = (const float*)d_in[6];
    const float* bq   = (const float*)d_in[7];
    const float* Wk   = (const float*)d_in[8];
    const float* bk   = (const float*)d_in[9];
    const float* Wv   = (const float*)d_in[10];
    const float* bv   = (const float*)d_in[11];
    const float* Wqg  = (const float*)d_in[12];
    const float* bqg  = (const float*)d_in[13];
    const float* Wkg  = (const float*)d_in[14];
    const float* bkg  = (const float*)d_in[15];
    const float* Wvg  = (const float*)d_in[16];
    const float* bvg  = (const float*)d_in[17];
    const float* Wo   = (const float*)d_in[18];
    const float* bo   = (const float*)d_in[19];
    const float* ln1s = (const float*)d_in[20];
    const float* ln1b = (const float*)d_in[21];
    const float* W1   = (const float*)d_in[22];
    const float* b1   = (const float*)d_in[23];
    const float* W2   = (const float*)d_in[24];
    const float* b2   = (const float*)d_in[25];
    const float* ln2s = (const float*)d_in[26];
    const float* ln2b = (const float*)d_in[27];
    const float* Wcls = (const float*)d_in[28];
    const float* bcls = (const float*)d_in[29];
    float* out = (float*)d_out;

    float *xp, *qp, *kp, *vp, *ap, *h1p, *scp, *qgp;
    cudaGetSymbolAddress((void**)&xp,  g_x);
    cudaGetSymbolAddress((void**)&qp,  g_q);
    cudaGetSymbolAddress((void**)&kp,  g_k);
    cudaGetSymbolAddress((void**)&vp,  g_v);
    cudaGetSymbolAddress((void**)&ap,  g_attn);
    cudaGetSymbolAddress((void**)&h1p, g_h1);
    cudaGetSymbolAddress((void**)&scp, g_sc);
    cudaGetSymbolAddress((void**)&qgp, g_qg);

    embed_ln_kernel<<<MROWS, 256>>>(ids, we, pe, lnes, lneb, xp);

    dim3 gemm_dm(CDM / 128, MROWS / 128);     // 6 x 64
    dim3 gemm_ff(CDFF / 128, MROWS / 128);    // 24 x 64

    for (int l = 0; l < CL; l++) {
        size_t woff = (size_t)l * CDM * CDM;
        size_t boff = (size_t)l * CDM;
        size_t w1off = (size_t)l * CDM * CDFF;
        size_t b1off = (size_t)l * CDFF;
        size_t w2off = (size_t)l * CDFF * CDM;

        gemm_bias_kernel<0><<<gemm_dm, 256>>>(xp, Wq + woff, bq + boff, qp, MROWS, CDM, CDM);
        gemm_bias_kernel<0><<<gemm_dm, 256>>>(xp, Wk + woff, bk + boff, kp, MROWS, CDM, CDM);
        gemm_bias_kernel<0><<<gemm_dm, 256>>>(xp, Wv + woff, bv + boff, vp, MROWS, CDM, CDM);

        band_scores_kernel<<<dim3(12, 4, CB * CH * CNB), 256>>>(qp, kp, am, scp);
        sg_kernel<<<(CB * CH * CS) / 8, 256>>>(qp, kp, am, scp);
        softmax_kernel<<<CB * CH * CS, 128>>>(scp);
        av_kernel<<<dim3(4, CB * CH * CNB), 256>>>(scp, vp, ap);

        qg_kernel<<<dim3(CDM / 256, CB), 256>>>(xp, Wqg + woff, bqg + boff, qgp);
        gemm_bias_kernel<0><<<gemm_dm, 256>>>(xp, Wkg + woff, bkg + boff, kp, MROWS, CDM, CDM);
        gemm_bias_kernel<0><<<gemm_dm, 256>>>(xp, Wvg + woff, bvg + boff, vp, MROWS, CDM, CDM);
        global_attn_kernel<<<dim3(CH, CB), 256>>>(qgp, kp, vp, am, ap);

        gemm_bias_kernel<0><<<gemm_dm, 256>>>(ap, Wo + woff, bo + boff, qp, MROWS, CDM, CDM);
        add_ln_kernel<<<MROWS, 256>>>(xp, qp, ln1s + boff, ln1b + boff);

        gemm_bias_kernel<1><<<gemm_ff, 256>>>(xp, W1 + w1off, b1 + b1off, h1p, MROWS, CDFF, CDM);
        gemm_bias_kernel<0><<<gemm_dm, 256>>>(h1p, W2 + w2off, b2 + boff, qp, MROWS, CDM, CDFF);
        add_ln_kernel<<<MROWS, 256>>>(xp, qp, ln2s + boff, ln2b + boff);
    }

    cls_kernel<<<4, 256>>>(xp, Wcls, bcls, out);
}

// round 4
// speedup vs baseline: 1.5081x; 1.5081x over previous
#include <cuda_runtime.h>
#include <cuda_bf16.h>
#include <math.h>
#include <stdint.h>

// ---------------- problem constants ----------------
#define CB   2
#define CS   4096
#define CH   12
#define CD   64
#define CW   256
#define CDM  768
#define CDFF 3072
#define CNB  16
#define CLW  769
#define CLP  772
#define CL   2
#define CNEG (-1000000000.0f)
#define CSCALE 0.125f

#define MROWS (CB*CS)    // 8192

// ---------------- scratch ----------------
__device__ float g_x   [MROWS*CDM];
__device__ float g_q   [MROWS*CDM];
__device__ float g_k   [MROWS*CDM];
__device__ float g_v   [MROWS*CDM];
__device__ float g_attn[MROWS*CDM];
__device__ float g_h1  [MROWS*CDFF];
__device__ float g_sc  [(size_t)CB*CH*CS*CLP];
__device__ float g_qg  [CB*CDM];
// bf16 split buffers (K' = 3K: A' = [hi|lo|hi], B' = [hi|hi|lo])
__device__ __nv_bfloat16 g_xb[(size_t)MROWS*3*CDM];
__device__ __nv_bfloat16 g_hb[(size_t)MROWS*3*CDFF];
__device__ __nv_bfloat16 g_wb[(size_t)3*CDFF*CDM];

// ---------------- helpers ----------------
__device__ __forceinline__ float gelu_tanh(float x) {
    float x3 = x * x * x;
    return 0.5f * x * (1.0f + tanhf(0.7978845608028654f * (x + 0.044715f * x3)));
}
__device__ __forceinline__ uint32_t smem_u32(const void* p) {
    uint32_t a;
    asm("{ .reg .u64 t; cvta.to.shared.u64 t, %1; cvt.u32.u64 %0, t; }" : "=r"(a) : "l"(p));
    return a;
}

// ================= split/convert kernels =================
__global__ void split_act_kernel(const float* __restrict__ A,
                                 __nv_bfloat16* __restrict__ Ap, int K) {
    int idx = blockIdx.x * 256 + threadIdx.x;
    int m = idx / K, k = idx - m * K;
    float a = A[idx];
    __nv_bfloat16 hi = __float2bfloat16_rn(a);
    __nv_bfloat16 lo = __float2bfloat16_rn(a - __bfloat162float(hi));
    size_t ro = (size_t)m * (3 * K);
    Ap[ro + k] = hi;
    Ap[ro + K + k] = lo;
    Ap[ro + 2 * K + k] = hi;
}

__global__ void split_wt_kernel(const float* __restrict__ W,
                                __nv_bfloat16* __restrict__ Wt, int K, int N) {
    __shared__ float t[32][33];
    int n0 = blockIdx.x * 32, k0 = blockIdx.y * 32;
    int tx = threadIdx.x, ty = threadIdx.y;   // 32 x 8
    #pragma unroll
    for (int r = 0; r < 4; r++) {
        int k = k0 + ty + r * 8;
        t[ty + r * 8][tx] = W[(size_t)k * N + n0 + tx];
    }
    __syncthreads();
    #pragma unroll
    for (int r = 0; r < 4; r++) {
        int n = n0 + ty + r * 8;
        int k = k0 + tx;
        float a = t[tx][ty + r * 8];
        __nv_bfloat16 hi = __float2bfloat16_rn(a);
        __nv_bfloat16 lo = __float2bfloat16_rn(a - __bfloat162float(hi));
        size_t ro = (size_t)n * (3 * K);
        Wt[ro + k] = hi;
        Wt[ro + K + k] = hi;
        Wt[ro + 2 * K + k] = lo;
    }
}

// ================= warp-MMA bf16 GEMM =================
// C[M,N] = A'[M,Kp] * Bt'[N,Kp]^T + bias (+GELU). 128x128 CTA tile, BK=32,
// 8 warps (2m x 4n), each warp 64x32 via m16n8k16. cp.async double buffer.
// SMEM rows padded to 80B for conflict-free ldmatrix.

#define AB_BYTES 10240          // 128 rows * 80B
#define BUF_BYTES (2*AB_BYTES)  // A + B per buffer

__device__ __forceinline__ void ldm_x4(uint32_t addr, uint32_t& r0, uint32_t& r1,
                                       uint32_t& r2, uint32_t& r3) {
    asm volatile("ldmatrix.sync.aligned.m8n8.x4.shared.b16 {%0,%1,%2,%3}, [%4];"
        : "=r"(r0), "=r"(r1), "=r"(r2), "=r"(r3) : "r"(addr));
}
__device__ __forceinline__ void mma_bf16(float* c, const uint32_t* a, const uint32_t* b) {
    asm volatile("mma.sync.aligned.m16n8k16.row.col.f32.bf16.bf16.f32 "
        "{%0,%1,%2,%3}, {%4,%5,%6,%7}, {%8,%9}, {%0,%1,%2,%3};"
        : "+f"(c[0]), "+f"(c[1]), "+f"(c[2]), "+f"(c[3])
        : "r"(a[0]), "r"(a[1]), "r"(a[2]), "r"(a[3]), "r"(b[0]), "r"(b[1]));
}

__global__ __launch_bounds__(256, 2)
void gemm_mma_kernel(const __nv_bfloat16* __restrict__ A,
                     const __nv_bfloat16* __restrict__ Bt,
                     const float* __restrict__ bias,
                     float* __restrict__ C,
                     int Kp, int N, int act) {
    __shared__ __align__(1024) char smem[2 * BUF_BYTES];
    uint32_t sb = smem_u32(smem);
    int tid = threadIdx.x;
    int wid = tid >> 5, lane = tid & 31;
    int m0 = blockIdx.y * 128, n0 = blockIdx.x * 128;
    int warp_m = (wid & 1) * 64;
    int warp_n = (wid >> 1) * 32;
    int NC = Kp / 32;

    const __nv_bfloat16* Ag = A  + (size_t)m0 * Kp;
    const __nv_bfloat16* Bg = Bt + (size_t)n0 * Kp;

    float acc[4][4][4];
    #pragma unroll
    for (int i = 0; i < 4; i++)
        #pragma unroll
        for (int j = 0; j < 4; j++)
            #pragma unroll
            for (int r = 0; r < 4; r++) acc[i][j][r] = 0.f;

    // cp.async tile loader: 512 A-chunks + 512 B-chunks of 16B; 2+2 per thread
    auto load_tile = [&](int c, int bf) {
        uint32_t abase = sb + bf * BUF_BYTES;
        uint32_t bbase = abase + AB_BYTES;
        const __nv_bfloat16* Ac = Ag + (size_t)c * 32;
        const __nv_bfloat16* Bc = Bg + (size_t)c * 32;
        #pragma unroll
        for (int i = 0; i < 2; i++) {
            int chunk = tid * 2 + i;            // 0..511
            int r = chunk >> 2, cc = (chunk & 3) * 8;
            uint32_t ad = abase + r * 80 + cc * 2;
            const void* as = Ac + (size_t)r * Kp + cc;
            asm volatile("cp.async.cg.shared.global [%0], [%1], 16;" :: "r"(ad), "l"(as));
            uint32_t bd = bbase + r * 80 + cc * 2;
            const void* bs = Bc + (size_t)r * Kp + cc;
            asm volatile("cp.async.cg.shared.global [%0], [%1], 16;" :: "r"(bd), "l"(bs));
        }
    };

    load_tile(0, 0);
    asm volatile("cp.async.commit_group;" ::: "memory");

    for (int c = 0; c < NC; c++) {
        int bf = c & 1;
        if (c + 1 < NC) load_tile(c + 1, bf ^ 1);
        asm volatile("cp.async.commit_group;" ::: "memory");
        asm volatile("cp.async.wait_group 1;" ::: "memory");
        __syncthreads();

        uint32_t abase = sb + bf * BUF_BYTES;
        uint32_t bbase = abase + AB_BYTES;
        int rsel = lane & 15, hsel = (lane >> 4) * 16;   // 8 elems * 2B

        #pragma unroll
        for (int ks = 0; ks < 2; ks++) {
            uint32_t a[4][4], b[4][2];
            #pragma unroll
            for (int mi = 0; mi < 4; mi++) {
                uint32_t ad = abase + (warp_m + mi * 16 + rsel) * 80 + ks * 32 + hsel;
                ldm_x4(ad, a[mi][0], a[mi][1], a[mi][2], a[mi][3]);
            }
            #pragma unroll
            for (int np = 0; np < 2; np++) {
                uint32_t r0, r1, r2, r3;
                uint32_t bd = bbase + (warp_n + np * 16 + rsel) * 80 + ks * 32 + hsel;
                ldm_x4(bd, r0, r1, r2, r3);
                b[np * 2 + 0][0] = r0; b[np * 2 + 0][1] = r2;
                b[np * 2 + 1][0] = r1; b[np * 2 + 1][1] = r3;
            }
            #pragma unroll
            for (int mi = 0; mi < 4; mi++)
                #pragma unroll
                for (int nj = 0; nj < 4; nj++)
                    mma_bf16(acc[mi][nj], a[mi], b[nj]);
        }
        __syncthreads();
    }

    // epilogue
    int g = lane >> 2, t = lane & 3;
    #pragma unroll
    for (int mi = 0; mi < 4; mi++) {
        int row0 = m0 + warp_m + mi * 16 + g;
        #pragma unroll
        for (int nj = 0; nj < 4; nj++) {
            int col = n0 + warp_n + nj * 8 + t * 2;
            float bx = bias[col], by = bias[col + 1];
            float v0 = acc[mi][nj][0] + bx, v1 = acc[mi][nj][1] + by;
            float v2 = acc[mi][nj][2] + bx, v3 = acc[mi][nj][3] + by;
            if (act) { v0 = gelu_tanh(v0); v1 = gelu_tanh(v1); v2 = gelu_tanh(v2); v3 = gelu_tanh(v3); }
            *(float2*)&C[(size_t)row0 * N + col]       = make_float2(v0, v1);
            *(float2*)&C[(size_t)(row0 + 8) * N + col] = make_float2(v2, v3);
        }
    }
}

// ================= non-GEMM kernels =================
__device__ __forceinline__ float block_reduce_sum256(float v, float* red) {
    int tid = threadIdx.x;
    red[tid] = v; __syncthreads();
    #pragma unroll
    for (int o = 128; o > 0; o >>= 1) {
        if (tid < o) red[tid] += red[tid + o];
        __syncthreads();
    }
    float r = red[0]; __syncthreads();
    return r;
}

__global__ void embed_ln_kernel(const int* __restrict__ ids,
                                const float* __restrict__ we,
                                const float* __restrict__ pe,
                                const float* __restrict__ gam,
                                const float* __restrict__ bet,
                                float* __restrict__ x) {
    __shared__ float red[256];
    int row = blockIdx.x;
    int s = row % CS;
    int id = ids[row];
    int tid = threadIdx.x;
    const float* wp = we + (size_t)id * CDM;
    const float* pp = pe + (size_t)s * CDM;
    float e[3];
    float sm = 0.f;
    #pragma unroll
    for (int i = 0; i < 3; i++) { int d = tid + i * 256; e[i] = wp[d] + pp[d]; sm += e[i]; }
    float mean = block_reduce_sum256(sm, red) * (1.0f / CDM);
    float vs = 0.f;
    #pragma unroll
    for (int i = 0; i < 3; i++) { float t = e[i] - mean; vs += t * t; }
    float var = block_reduce_sum256(vs, red) * (1.0f / CDM);
    float inv = rsqrtf(var + 1e-5f);
    float* xr = x + (size_t)row * CDM;
    #pragma unroll
    for (int i = 0; i < 3; i++) { int d = tid + i * 256; xr[d] = (e[i] - mean) * inv * gam[d] + bet[d]; }
}

__global__ void add_ln_kernel(float* __restrict__ x,
                              const float* __restrict__ y,
                              const float* __restrict__ gam,
                              const float* __restrict__ bet) {
    __shared__ float red[256];
    int row = blockIdx.x;
    int tid = threadIdx.x;
    float* xr = x + (size_t)row * CDM;
    const float* yr = y + (size_t)row * CDM;
    float e[3];
    float sm = 0.f;
    #pragma unroll
    for (int i = 0; i < 3; i++) { int d = tid + i * 256; e[i] = xr[d] + yr[d]; sm += e[i]; }
    float mean = block_reduce_sum256(sm, red) * (1.0f / CDM);
    float vs = 0.f;
    #pragma unroll
    for (int i = 0; i < 3; i++) { float t = e[i] - mean; vs += t * t; }
    float var = block_reduce_sum256(vs, red) * (1.0f / CDM);
    float inv = rsqrtf(var + 1e-5f);
    #pragma unroll
    for (int i = 0; i < 3; i++) { int d = tid + i * 256; xr[d] = (e[i] - mean) * inv * gam[d] + bet[d]; }
}

__global__ __launch_bounds__(256)
void band_scores_kernel(const float* __restrict__ q,
                        const float* __restrict__ k,
                        const int* __restrict__ am,
                        float* __restrict__ sc) {
    __shared__ float Qs[64][64];
    __shared__ float Ks[64][64];
    int z = blockIdx.z;
    int n = z % CNB;
    int h = (z / CNB) % CH;
    int b = z / (CNB * CH);
    int qt = blockIdx.y;
    int kt = blockIdx.x;
    int tid = threadIdx.x;

    int base_s    = n * CW + qt * 64;
    int base_kpos = n * CW - CW + kt * 64;

    #pragma unroll
    for (int i = 0; i < 4; i++) {
        int sid = tid + i * 256;
        int r = sid >> 4, c4 = (sid & 15) << 2;
        float4 v = *(const float4*)&q[((size_t)(b * CS + base_s + r)) * CDM + h * 64 + c4];
        Qs[c4 + 0][r] = v.x * CSCALE;
        Qs[c4 + 1][r] = v.y * CSCALE;
        Qs[c4 + 2][r] = v.z * CSCALE;
        Qs[c4 + 3][r] = v.w * CSCALE;
    }
    #pragma unroll
    for (int i = 0; i < 4; i++) {
        int sid = tid + i * 256;
        int r = sid >> 4, c4 = (sid & 15) << 2;
        int kpos = base_kpos + r;
        float4 v = make_float4(0.f, 0.f, 0.f, 0.f);
        if (kpos >= 0 && kpos < CS)
            v = *(const float4*)&k[((size_t)(b * CS + kpos)) * CDM + h * 64 + c4];
        Ks[c4 + 0][r] = v.x;
        Ks[c4 + 1][r] = v.y;
        Ks[c4 + 2][r] = v.z;
        Ks[c4 + 3][r] = v.w;
    }
    __syncthreads();

    int tx = tid & 15, ty = tid >> 4;
    float acc[4][4];
    #pragma unroll
    for (int i = 0; i < 4; i++)
        #pragma unroll
        for (int j = 0; j < 4; j++) acc[i][j] = 0.f;

    #pragma unroll 8
    for (int kk = 0; kk < 64; kk++) {
        float a[4], bb[4];
        *(float4*)a  = *(const float4*)&Qs[kk][ty * 4];
        *(float4*)bb = *(const float4*)&Ks[kk][tx * 4];
        #pragma unroll
        for (int i = 0; i < 4; i++)
            #pragma unroll
            for (int j = 0; j < 4; j++)
                acc[i][j] += a[i] * bb[j];
    }

    #pragma unroll
    for (int i = 0; i < 4; i++) {
        int qi = qt * 64 + ty * 4 + i;
        int s  = n * CW + qi;
        size_t rowbase = ((size_t)((b * CH + h) * CS + s)) * CLP;
        #pragma unroll
        for (int j = 0; j < 4; j++) {
            int kj = kt * 64 + tx * 4 + j;
            int kpos = n * CW - CW + kj;
            bool ok = (kj >= qi) && (kj <= qi + 2 * CW) &&
                      (kpos >= 0) && (kpos < CS) && (kpos != 0) &&
                      (am[b * CS + kpos] > 0);
            sc[rowbase + kj] = ok ? acc[i][j] : CNEG;
        }
    }
}

__global__ void sg_kernel(const float* __restrict__ q,
                          const float* __restrict__ k,
                          const int* __restrict__ am,
                          float* __restrict__ sc) {
    int gw = (blockIdx.x * blockDim.x + threadIdx.x) >> 5;
    int lane = threadIdx.x & 31;
    if (gw >= CB * CH * CS) return;
    int s = gw % CS;
    int h = (gw / CS) % CH;
    int b = gw / (CS * CH);
    float val = CNEG;
    if (am[b * CS] > 0) {
        const float* qp = &q[((size_t)(b * CS + s)) * CDM + h * 64];
        const float* kp = &k[((size_t)(b * CS)) * CDM + h * 64];
        float p = qp[lane] * kp[lane] + qp[lane + 32] * kp[lane + 32];
        #pragma unroll
        for (int o = 16; o > 0; o >>= 1) p += __shfl_xor_sync(0xffffffffu, p, o);
        val = p * CSCALE;
    }
    if (lane == 0) sc[(size_t)gw * CLP + 768] = val;
}

__global__ void softmax_kernel(float* __restrict__ sc) {
    __shared__ float row[CLW];
    __shared__ float red[128];
    size_t r = blockIdx.x;
    float* p = sc + r * CLP;
    int tid = threadIdx.x;
    float mx = -1e30f;
    for (int i = tid; i < CLW; i += 128) { row[i] = p[i]; mx = fmaxf(mx, row[i]); }
    red[tid] = mx; __syncthreads();
    #pragma unroll
    for (int o = 64; o > 0; o >>= 1) {
        if (tid < o) red[tid] = fmaxf(red[tid], red[tid + o]);
        __syncthreads();
    }
    mx = red[0]; __syncthreads();
    float sm = 0.f;
    for (int i = tid; i < CLW; i += 128) {
        float e = __expf(row[i] - mx);
        row[i] = e; sm += e;
    }
    red[tid] = sm; __syncthreads();
    #pragma unroll
    for (int o = 64; o > 0; o >>= 1) {
        if (tid < o) red[tid] += red[tid + o];
        __syncthreads();
    }
    float inv = 1.0f / red[0];
    for (int i = tid; i < CLW; i += 128) p[i] = row[i] * inv;
}

__global__ __launch_bounds__(256)
void av_kernel(const float* __restrict__ sc,
               const float* __restrict__ v,
               float* __restrict__ out) {
    __shared__ float As[64][64];
    __shared__ float Vs[64][64];
    int z = blockIdx.y;
    int n = z % CNB;
    int h = (z / CNB) % CH;
    int b = z / (CNB * CH);
    int qt = blockIdx.x;
    int tid = threadIdx.x;
    int tx = tid & 15, ty = tid >> 4;

    float acc[4][4];
    #pragma unroll
    for (int i = 0; i < 4; i++)
        #pragma unroll
        for (int j = 0; j < 4; j++) acc[i][j] = 0.f;

    for (int kc = 0; kc < 12; kc++) {
        #pragma unroll
        for (int i = 0; i < 4; i++) {
            int sid = tid + i * 256;
            int r = sid >> 4, c4 = (sid & 15) << 2;
            int s = n * CW + qt * 64 + r;
            float4 a4 = *(const float4*)&sc[((size_t)((b * CH + h) * CS + s)) * CLP + kc * 64 + c4];
            As[c4 + 0][r] = a4.x;
            As[c4 + 1][r] = a4.y;
            As[c4 + 2][r] = a4.z;
            As[c4 + 3][r] = a4.w;
            int kpos = n * CW - CW + kc * 64 + r;
            float4 v4 = make_float4(0.f, 0.f, 0.f, 0.f);
            if (kpos >= 0 && kpos < CS)
                v4 = *(const float4*)&v[((size_t)(b * CS + kpos)) * CDM + h * 64 + c4];
            *(float4*)&Vs[r][c4] = v4;
        }
        __syncthreads();
        #pragma unroll 8
        for (int kk = 0; kk < 64; kk++) {
            float a[4], bb[4];
            *(float4*)a  = *(const float4*)&As[kk][ty * 4];
            *(float4*)bb = *(const float4*)&Vs[kk][tx * 4];
            #pragma unroll
            for (int i = 0; i < 4; i++)
                #pragma unroll
                for (int j = 0; j < 4; j++)
                    acc[i][j] += a[i] * bb[j];
        }
        __syncthreads();
    }

    #pragma unroll
    for (int i = 0; i < 4; i++) {
        int s = n * CW + qt * 64 + ty * 4 + i;
        float g = sc[((size_t)((b * CH + h) * CS + s)) * CLP + 768];
        #pragma unroll
        for (int j = 0; j < 4; j++) {
            int d = tx * 4 + j;
            float v0 = v[((size_t)(b * CS)) * CDM + h * 64 + d];
            out[((size_t)(b * CS + s)) * CDM + h * 64 + d] = acc[i][j] + g * v0;
        }
    }
}

__global__ void qg_kernel(const float* __restrict__ x,
                          const float* __restrict__ Wqg,
                          const float* __restrict__ bqg,
                          float* __restrict__ qg) {
    int nidx = blockIdx.x * 256 + threadIdx.x;
    int b = blockIdx.y;
    const float* xr = x + (size_t)(b * CS) * CDM;
    float acc = bqg[nidx];
    for (int kk = 0; kk < CDM; kk++)
        acc += xr[kk] * Wqg[(size_t)kk * CDM + nidx];
    qg[b * CDM + nidx] = acc * CSCALE;
}

__global__ void global_attn_kernel(const float* __restrict__ qg,
                                   const float* __restrict__ kg,
                                   const float* __restrict__ vg,
                                   const int* __restrict__ am,
                                   float* __restrict__ out) {
    __shared__ float scs[CS];
    __shared__ float red[256];
    __shared__ float qs[64];
    int h = blockIdx.x, b = blockIdx.y;
    int tid = threadIdx.x;
    if (tid < 64) qs[tid] = qg[b * CDM + h * 64 + tid];
    __syncthreads();

    float mx = -1e30f;
    for (int s = tid; s < CS; s += 256) {
        const float* kp = &kg[((size_t)(b * CS + s)) * CDM + h * 64];
        float dd = 0.f;
        #pragma unroll
        for (int e = 0; e < 64; e++) dd += qs[e] * kp[e];
        if (am[b * CS + s] <= 0) dd = CNEG;
        scs[s] = dd;
        mx = fmaxf(mx, dd);
    }
    red[tid] = mx; __syncthreads();
    #pragma unroll
    for (int o = 128; o > 0; o >>= 1) {
        if (tid < o) red[tid] = fmaxf(red[tid], red[tid + o]);
        __syncthreads();
    }
    mx = red[0]; __syncthreads();

    float sm = 0.f;
    for (int s = tid; s < CS; s += 256) {
        float e = __expf(scs[s] - mx);
        scs[s] = e; sm += e;
    }
    float tot = block_reduce_sum256(sm, red);
    float inv = 1.0f / tot;
    __syncthreads();

    int d = tid & 63, sl = tid >> 6;
    float acc = 0.f;
    for (int s = sl * 1024; s < (sl + 1) * 1024; s++)
        acc += scs[s] * vg[((size_t)(b * CS + s)) * CDM + h * 64 + d];
    red[tid] = acc; __syncthreads();
    if (sl == 0) {
        float t = red[d] + red[64 + d] + red[128 + d] + red[192 + d];
        out[((size_t)(b * CS)) * CDM + h * 64 + d] = t * inv;
    }
}

__global__ void cls_kernel(const float* __restrict__ x,
                           const float* __restrict__ Wc,
                           const float* __restrict__ bc,
                           float* __restrict__ out) {
    __shared__ float red[256];
    int b = blockIdx.x >> 1, c = blockIdx.x & 1;
    int tid = threadIdx.x;
    const float* xr = x + (size_t)(b * CS) * CDM;
    float acc = 0.f;
    for (int d = tid; d < CDM; d += 256) acc += xr[d] * Wc[d * 2 + c];
    float tot = block_reduce_sum256(acc, red);
    if (tid == 0) out[b * 2 + c] = tot + bc[c];
}

// ================= launch =================
extern "C" void kernel_launch(void* const* d_in, const int* in_sizes, int n_in,
                              void* d_out, int out_size) {
    const int*   ids  = (const int*)d_in[0];
    const int*   am   = (const int*)d_in[1];
    const float* we   = (const float*)d_in[2];
    const float* pe   = (const float*)d_in[3];
    const float* lnes = (const float*)d_in[4];
    const float* lneb = (const float*)d_in[5];
    const float* Wq   = (const float*)d_in[6];
    const float* bq   = (const float*)d_in[7];
    const float* Wk   = (const float*)d_in[8];
    const float* bk   = (const float*)d_in[9];
    const float* Wv   = (const float*)d_in[10];
    const float* bv   = (const float*)d_in[11];
    const float* Wqg  = (const float*)d_in[12];
    const float* bqg  = (const float*)d_in[13];
    const float* Wkg  = (const float*)d_in[14];
    const float* bkg  = (const float*)d_in[15];
    const float* Wvg  = (const float*)d_in[16];
    const float* bvg  = (const float*)d_in[17];
    const float* Wo   = (const float*)d_in[18];
    const float* bo   = (const float*)d_in[19];
    const float* ln1s = (const float*)d_in[20];
    const float* ln1b = (const float*)d_in[21];
    const float* W1   = (const float*)d_in[22];
    const float* b1   = (const float*)d_in[23];
    const float* W2   = (const float*)d_in[24];
    const float* b2   = (const float*)d_in[25];
    const float* ln2s = (const float*)d_in[26];
    const float* ln2b = (const float*)d_in[27];
    const float* Wcls = (const float*)d_in[28];
    const float* bcls = (const float*)d_in[29];
    float* out = (float*)d_out;

    float *xp, *qp, *kp, *vp, *ap, *h1p, *scp, *qgp;
    __nv_bfloat16 *xbp, *hbp, *wbp;
    cudaGetSymbolAddress((void**)&xp,  g_x);
    cudaGetSymbolAddress((void**)&qp,  g_q);
    cudaGetSymbolAddress((void**)&kp,  g_k);
    cudaGetSymbolAddress((void**)&vp,  g_v);
    cudaGetSymbolAddress((void**)&ap,  g_attn);
    cudaGetSymbolAddress((void**)&h1p, g_h1);
    cudaGetSymbolAddress((void**)&scp, g_sc);
    cudaGetSymbolAddress((void**)&qgp, g_qg);
    cudaGetSymbolAddress((void**)&xbp, g_xb);
    cudaGetSymbolAddress((void**)&hbp, g_hb);
    cudaGetSymbolAddress((void**)&wbp, g_wb);

    embed_ln_kernel<<<MROWS, 256>>>(ids, we, pe, lnes, lneb, xp);

    dim3 g_dm(CDM / 128, MROWS / 128);    // (6, 64)
    dim3 g_ff(CDFF / 128, MROWS / 128);   // (24, 64)
    dim3 wt_dm(CDM / 32, CDM / 32);
    dim3 wt_b(32, 8);
    int actK  = MROWS * CDM / 256;
    int actKf = MROWS * CDFF / 256;

    for (int l = 0; l < CL; l++) {
        size_t woff = (size_t)l * CDM * CDM;
        size_t boff = (size_t)l * CDM;
        size_t w1off = (size_t)l * CDM * CDFF;
        size_t b1off = (size_t)l * CDFF;
        size_t w2off = (size_t)l * CDFF * CDM;

        split_act_kernel<<<actK, 256>>>(xp, xbp, CDM);

        split_wt_kernel<<<wt_dm, wt_b>>>(Wq + woff, wbp, CDM, CDM);
        gemm_mma_kernel<<<g_dm, 256>>>(xbp, wbp, bq + boff, qp, 3 * CDM, CDM, 0);
        split_wt_kernel<<<wt_dm, wt_b>>>(Wk + woff, wbp, CDM, CDM);
        gemm_mma_kernel<<<g_dm, 256>>>(xbp, wbp, bk + boff, kp, 3 * CDM, CDM, 0);
        split_wt_kernel<<<wt_dm, wt_b>>>(Wv + woff, wbp, CDM, CDM);
        gemm_mma_kernel<<<g_dm, 256>>>(xbp, wbp, bv + boff, vp, 3 * CDM, CDM, 0);

        band_scores_kernel<<<dim3(12, 4, CB * CH * CNB), 256>>>(qp, kp, am, scp);
        sg_kernel<<<(CB * CH * CS) / 8, 256>>>(qp, kp, am, scp);
        softmax_kernel<<<CB * CH * CS, 128>>>(scp);
        av_kernel<<<dim3(4, CB * CH * CNB), 256>>>(scp, vp, ap);

        qg_kernel<<<dim3(CDM / 256, CB), 256>>>(xp, Wqg + woff, bqg + boff, qgp);
        split_wt_kernel<<<wt_dm, wt_b>>>(Wkg + woff, wbp, CDM, CDM);
        gemm_mma_kernel<<<g_dm, 256>>>(xbp, wbp, bkg + boff, kp, 3 * CDM, CDM, 0);
        split_wt_kernel<<<wt_dm, wt_b>>>(Wvg + woff, wbp, CDM, CDM);
        gemm_mma_kernel<<<g_dm, 256>>>(xbp, wbp, bvg + boff, vp, 3 * CDM, CDM, 0);
        global_attn_kernel<<<dim3(CH, CB), 256>>>(qgp, kp, vp, am, ap);

        split_act_kernel<<<actK, 256>>>(ap, xbp, CDM);
        split_wt_kernel<<<wt_dm, wt_b>>>(Wo + woff, wbp, CDM, CDM);
        gemm_mma_kernel<<<g_dm, 256>>>(xbp, wbp, bo + boff, qp, 3 * CDM, CDM, 0);
        add_ln_kernel<<<MROWS, 256>>>(xp, qp, ln1s + boff, ln1b + boff);

        split_act_kernel<<<actK, 256>>>(xp, xbp, CDM);
        split_wt_kernel<<<dim3(CDFF / 32, CDM / 32), wt_b>>>(W1 + w1off, wbp, CDM, CDFF);
        gemm_mma_kernel<<<g_ff, 256>>>(xbp, wbp, b1 + b1off, h1p, 3 * CDM, CDFF, 1);

        split_act_kernel<<<actKf, 256>>>(h1p, hbp, CDFF);
        split_wt_kernel<<<dim3(CDM / 32, CDFF / 32), wt_b>>>(W2 + w2off, wbp, CDFF, CDM);
        gemm_mma_kernel<<<g_dm, 256>>>(hbp, wbp, b2 + boff, qp, 3 * CDFF, CDM, 0);
        add_ln_kernel<<<MROWS, 256>>>(xp, qp, ln2s + boff, ln2b + boff);
    }

    cls_kernel<<<4, 256>>>(xp, Wcls, bcls, out);
}

// round 5
// speedup vs baseline: 1.7661x; 1.1711x over previous
#include <cuda_runtime.h>
#include <cuda_bf16.h>
#include <math.h>
#include <stdint.h>

// ---------------- problem constants ----------------
#define CB   2
#define CS   4096
#define CH   12
#define CD   64
#define CW   256
#define CDM  768
#define CDFF 3072
#define CNB  16
#define CL   2
#define CNEG (-1000000000.0f)
#define CSCALE 0.125f

#define MROWS (CB*CS)    // 8192

// ---------------- scratch ----------------
__device__ float g_x   [MROWS*CDM];
__device__ float g_q   [MROWS*CDM];
__device__ float g_k   [MROWS*CDM];
__device__ float g_v   [MROWS*CDM];
__device__ float g_attn[MROWS*CDM];
__device__ float g_h1  [MROWS*CDFF];
__device__ float g_qg  [CB*CDM];
// bf16 split buffers (K' = 3K: A' = [hi|lo|hi], B' = [hi|hi|lo])
__device__ __nv_bfloat16 g_xb[(size_t)MROWS*3*CDM];
__device__ __nv_bfloat16 g_hb[(size_t)MROWS*3*CDFF];
__device__ __nv_bfloat16 g_wb[(size_t)3*CDFF*CDM];

// ---------------- helpers ----------------
__device__ __forceinline__ float gelu_tanh(float x) {
    float x3 = x * x * x;
    return 0.5f * x * (1.0f + tanhf(0.7978845608028654f * (x + 0.044715f * x3)));
}
__device__ __forceinline__ uint32_t smem_u32(const void* p) {
    uint32_t a;
    asm("{ .reg .u64 t; cvta.to.shared.u64 t, %1; cvt.u32.u64 %0, t; }" : "=r"(a) : "l"(p));
    return a;
}

// ================= split/convert kernels =================
__global__ void split_act_kernel(const float* __restrict__ A,
                                 __nv_bfloat16* __restrict__ Ap, int K) {
    int idx = blockIdx.x * 256 + threadIdx.x;
    int m = idx / K, k = idx - m * K;
    float a = A[idx];
    __nv_bfloat16 hi = __float2bfloat16_rn(a);
    __nv_bfloat16 lo = __float2bfloat16_rn(a - __bfloat162float(hi));
    size_t ro = (size_t)m * (3 * K);
    Ap[ro + k] = hi;
    Ap[ro + K + k] = lo;
    Ap[ro + 2 * K + k] = hi;
}

__global__ void split_wt_kernel(const float* __restrict__ W,
                                __nv_bfloat16* __restrict__ Wt, int K, int N) {
    __shared__ float t[32][33];
    int n0 = blockIdx.x * 32, k0 = blockIdx.y * 32;
    int tx = threadIdx.x, ty = threadIdx.y;   // 32 x 8
    #pragma unroll
    for (int r = 0; r < 4; r++) {
        int k = k0 + ty + r * 8;
        t[ty + r * 8][tx] = W[(size_t)k * N + n0 + tx];
    }
    __syncthreads();
    #pragma unroll
    for (int r = 0; r < 4; r++) {
        int n = n0 + ty + r * 8;
        int k = k0 + tx;
        float a = t[tx][ty + r * 8];
        __nv_bfloat16 hi = __float2bfloat16_rn(a);
        __nv_bfloat16 lo = __float2bfloat16_rn(a - __bfloat162float(hi));
        size_t ro = (size_t)n * (3 * K);
        Wt[ro + k] = hi;
        Wt[ro + K + k] = hi;
        Wt[ro + 2 * K + k] = lo;
    }
}

// ================= warp-MMA bf16 GEMM (3-stage cp.async pipeline) ==========
#define AB_BYTES 10240          // 128 rows * 80B
#define BUF_BYTES (2*AB_BYTES)  // A + B per stage
#define GSM_TOT (3*BUF_BYTES)   // 61440

__device__ __forceinline__ void ldm_x4(uint32_t addr, uint32_t& r0, uint32_t& r1,
                                       uint32_t& r2, uint32_t& r3) {
    asm volatile("ldmatrix.sync.aligned.m8n8.x4.shared.b16 {%0,%1,%2,%3}, [%4];"
        : "=r"(r0), "=r"(r1), "=r"(r2), "=r"(r3) : "r"(addr));
}
__device__ __forceinline__ void mma_bf16(float* c, const uint32_t* a, const uint32_t* b) {
    asm volatile("mma.sync.aligned.m16n8k16.row.col.f32.bf16.bf16.f32 "
        "{%0,%1,%2,%3}, {%4,%5,%6,%7}, {%8,%9}, {%0,%1,%2,%3};"
        : "+f"(c[0]), "+f"(c[1]), "+f"(c[2]), "+f"(c[3])
        : "r"(a[0]), "r"(a[1]), "r"(a[2]), "r"(a[3]), "r"(b[0]), "r"(b[1]));
}

__global__ __launch_bounds__(256)
void gemm_mma_kernel(const __nv_bfloat16* __restrict__ A,
                     const __nv_bfloat16* __restrict__ Bt,
                     const float* __restrict__ bias,
                     float* __restrict__ C,
                     int Kp, int N, int act) {
    extern __shared__ __align__(1024) char smem[];
    uint32_t sb = smem_u32(smem);
    int tid = threadIdx.x;
    int wid = tid >> 5, lane = tid & 31;
    int m0 = blockIdx.y * 128, n0 = blockIdx.x * 128;
    int warp_m = (wid & 1) * 64;
    int warp_n = (wid >> 1) * 32;
    int NC = Kp / 32;

    const __nv_bfloat16* Ag = A  + (size_t)m0 * Kp;
    const __nv_bfloat16* Bg = Bt + (size_t)n0 * Kp;

    float acc[4][4][4];
    #pragma unroll
    for (int i = 0; i < 4; i++)
        #pragma unroll
        for (int j = 0; j < 4; j++)
            #pragma unroll
            for (int r = 0; r < 4; r++) acc[i][j][r] = 0.f;

    auto load_tile = [&](int c, int bf) {
        uint32_t abase = sb + bf * BUF_BYTES;
        uint32_t bbase = abase + AB_BYTES;
        const __nv_bfloat16* Ac = Ag + (size_t)c * 32;
        const __nv_bfloat16* Bc = Bg + (size_t)c * 32;
        #pragma unroll
        for (int i = 0; i < 2; i++) {
            int chunk = tid * 2 + i;            // 0..511
            int r = chunk >> 2, cc = (chunk & 3) * 8;
            uint32_t ad = abase + r * 80 + cc * 2;
            const void* as = Ac + (size_t)r * Kp + cc;
            asm volatile("cp.async.cg.shared.global [%0], [%1], 16;" :: "r"(ad), "l"(as));
            uint32_t bd = bbase + r * 80 + cc * 2;
            const void* bs = Bc + (size_t)r * Kp + cc;
            asm volatile("cp.async.cg.shared.global [%0], [%1], 16;" :: "r"(bd), "l"(bs));
        }
    };

    load_tile(0, 0);
    asm volatile("cp.async.commit_group;" ::: "memory");
    load_tile(1, 1);
    asm volatile("cp.async.commit_group;" ::: "memory");

    int bf = 0;
    for (int c = 0; c < NC; c++) {
        asm volatile("cp.async.wait_group 1;" ::: "memory");
        __syncthreads();
        // prefetch chunk c+2 into the buffer freed by compute(c-1)
        int nbf = bf + 2; if (nbf >= 3) nbf -= 3;
        if (c + 2 < NC) load_tile(c + 2, nbf);
        asm volatile("cp.async.commit_group;" ::: "memory");

        uint32_t abase = sb + bf * BUF_BYTES;
        uint32_t bbase = abase + AB_BYTES;
        int rsel = lane & 15, hsel = (lane >> 4) * 16;

        #pragma unroll
        for (int ks = 0; ks < 2; ks++) {
            uint32_t a[4][4], b[4][2];
            #pragma unroll
            for (int mi = 0; mi < 4; mi++) {
                uint32_t ad = abase + (warp_m + mi * 16 + rsel) * 80 + ks * 32 + hsel;
                ldm_x4(ad, a[mi][0], a[mi][1], a[mi][2], a[mi][3]);
            }
            #pragma unroll
            for (int np = 0; np < 2; np++) {
                uint32_t r0, r1, r2, r3;
                uint32_t bd = bbase + (warp_n + np * 16 + rsel) * 80 + ks * 32 + hsel;
                ldm_x4(bd, r0, r1, r2, r3);
                b[np * 2 + 0][0] = r0; b[np * 2 + 0][1] = r2;
                b[np * 2 + 1][0] = r1; b[np * 2 + 1][1] = r3;
            }
            #pragma unroll
            for (int mi = 0; mi < 4; mi++)
                #pragma unroll
                for (int nj = 0; nj < 4; nj++)
                    mma_bf16(acc[mi][nj], a[mi], b[nj]);
        }
        bf++; if (bf >= 3) bf = 0;
    }

    // epilogue
    int g = lane >> 2, t = lane & 3;
    #pragma unroll
    for (int mi = 0; mi < 4; mi++) {
        int row0 = m0 + warp_m + mi * 16 + g;
        #pragma unroll
        for (int nj = 0; nj < 4; nj++) {
            int col = n0 + warp_n + nj * 8 + t * 2;
            float bx = bias[col], by = bias[col + 1];
            float v0 = acc[mi][nj][0] + bx, v1 = acc[mi][nj][1] + by;
            float v2 = acc[mi][nj][2] + bx, v3 = acc[mi][nj][3] + by;
            if (act) { v0 = gelu_tanh(v0); v1 = gelu_tanh(v1); v2 = gelu_tanh(v2); v3 = gelu_tanh(v3); }
            *(float2*)&C[(size_t)row0 * N + col]       = make_float2(v0, v1);
            *(float2*)&C[(size_t)(row0 + 8) * N + col] = make_float2(v2, v3);
        }
    }
}

// ================= fused flash band attention =================
// One kernel replaces band_scores + sg + softmax + av. Online softmax over
// the 768-key band + global column; out = softmax(scores) @ [Vwin; v0].
// grid: (4 qtiles, B*H*NB), 256 threads. Thread (ty,tx): rows ty*4+i, cols tx*4+j.
#define FS_Q  0          // Qs[64][64] floats, [d][qi]
#define FS_K  4096       // Ks[64][64]  [d][kj]
#define FS_V  8192       // Vs[64][64]  [kj][d]
#define FS_P  12288      // Ps[64][72]  [qi][kj], stride 72
#define FS_K0 16896      // k0s[64]
#define FS_V0 16960      // v0s[64]
#define FS_TOT ((16960 + 64) * 4)   // bytes = 68096

__global__ __launch_bounds__(256)
void flash_band_kernel(const float* __restrict__ q,
                       const float* __restrict__ k,
                       const float* __restrict__ v,
                       const int* __restrict__ am,
                       float* __restrict__ out) {
    extern __shared__ float fsm[];
    int z = blockIdx.y;
    int n = z % CNB;
    int h = (z / CNB) % CH;
    int b = z / (CNB * CH);
    int qt = blockIdx.x;
    int tid = threadIdx.x;
    int tx = tid & 15, ty = tid >> 4;

    int base_s    = n * CW + qt * 64;
    int base_kpos = n * CW - CW;

    // load Q (scaled), k0, v0
    #pragma unroll
    for (int i = 0; i < 4; i++) {
        int sid = tid + i * 256;
        int r = sid >> 4, c4 = (sid & 15) << 2;
        float4 vq = *(const float4*)&q[((size_t)(b * CS + base_s + r)) * CDM + h * 64 + c4];
        fsm[FS_Q + (c4 + 0) * 64 + r] = vq.x * CSCALE;
        fsm[FS_Q + (c4 + 1) * 64 + r] = vq.y * CSCALE;
        fsm[FS_Q + (c4 + 2) * 64 + r] = vq.z * CSCALE;
        fsm[FS_Q + (c4 + 3) * 64 + r] = vq.w * CSCALE;
    }
    if (tid < 64) {
        fsm[FS_K0 + tid] = k[((size_t)(b * CS)) * CDM + h * 64 + tid];
        fsm[FS_V0 + tid] = v[((size_t)(b * CS)) * CDM + h * 64 + tid];
    }

    float mst[4], lst[4], acc[4][4];
    #pragma unroll
    for (int i = 0; i < 4; i++) {
        mst[i] = -1e30f; lst[i] = 0.f;
        #pragma unroll
        for (int j = 0; j < 4; j++) acc[i][j] = 0.f;
    }
    int am0 = am[b * CS];

    for (int kc = 0; kc < 12; kc++) {
        __syncthreads();   // protect Ks/Vs/Ps from previous iter's readers
        // load K chunk [d][kj], V chunk [kj][d]
        #pragma unroll
        for (int i = 0; i < 4; i++) {
            int sid = tid + i * 256;
            int r = sid >> 4, c4 = (sid & 15) << 2;
            int kpos = base_kpos + kc * 64 + r;
            float4 vk = make_float4(0.f, 0.f, 0.f, 0.f);
            float4 vv = make_float4(0.f, 0.f, 0.f, 0.f);
            if (kpos >= 0 && kpos < CS) {
                vk = *(const float4*)&k[((size_t)(b * CS + kpos)) * CDM + h * 64 + c4];
                vv = *(const float4*)&v[((size_t)(b * CS + kpos)) * CDM + h * 64 + c4];
            }
            fsm[FS_K + (c4 + 0) * 64 + r] = vk.x;
            fsm[FS_K + (c4 + 1) * 64 + r] = vk.y;
            fsm[FS_K + (c4 + 2) * 64 + r] = vk.z;
            fsm[FS_K + (c4 + 3) * 64 + r] = vk.w;
            *(float4*)&fsm[FS_V + r * 64 + c4] = vv;
        }
        __syncthreads();

        // S = Q . K^T  (64x64 tile)
        float s[4][4];
        #pragma unroll
        for (int i = 0; i < 4; i++)
            #pragma unroll
            for (int j = 0; j < 4; j++) s[i][j] = 0.f;
        #pragma unroll 8
        for (int kk = 0; kk < 64; kk++) {
            float a[4], bb[4];
            *(float4*)a  = *(const float4*)&fsm[FS_Q + kk * 64 + ty * 4];
            *(float4*)bb = *(const float4*)&fsm[FS_K + kk * 64 + tx * 4];
            #pragma unroll
            for (int i = 0; i < 4; i++)
                #pragma unroll
                for (int j = 0; j < 4; j++)
                    s[i][j] += a[i] * bb[j];
        }

        // mask
        #pragma unroll
        for (int i = 0; i < 4; i++) {
            int qi = qt * 64 + ty * 4 + i;
            #pragma unroll
            for (int j = 0; j < 4; j++) {
                int kj = kc * 64 + tx * 4 + j;
                int kpos = base_kpos + kj;
                bool ok = (kj >= qi) && (kj <= qi + 2 * CW) &&
                          (kpos >= 0) && (kpos < CS) && (kpos != 0) &&
                          (am[b * CS + (kpos & (CS - 1))] > 0);
                if (!ok) s[i][j] = CNEG;
            }
        }

        // online softmax update
        #pragma unroll
        for (int i = 0; i < 4; i++) {
            float cm = fmaxf(fmaxf(s[i][0], s[i][1]), fmaxf(s[i][2], s[i][3]));
            #pragma unroll
            for (int o = 1; o < 16; o <<= 1)
                cm = fmaxf(cm, __shfl_xor_sync(0xffffffffu, cm, o));
            float nm = fmaxf(mst[i], cm);
            float alpha = __expf(mst[i] - nm);
            mst[i] = nm;
            float rs = 0.f;
            #pragma unroll
            for (int j = 0; j < 4; j++) {
                s[i][j] = __expf(s[i][j] - nm);
                rs += s[i][j];
            }
            #pragma unroll
            for (int o = 1; o < 16; o <<= 1)
                rs += __shfl_xor_sync(0xffffffffu, rs, o);
            lst[i] = lst[i] * alpha + rs;
            #pragma unroll
            for (int j = 0; j < 4; j++) acc[i][j] *= alpha;
            // store P row
            int qi = ty * 4 + i;
            *(float4*)&fsm[FS_P + qi * 72 + tx * 4] = make_float4(s[i][0], s[i][1], s[i][2], s[i][3]);
        }
        __syncthreads();

        // acc += P . V
        #pragma unroll 4
        for (int kk = 0; kk < 64; kk++) {
            float bb[4];
            *(float4*)bb = *(const float4*)&fsm[FS_V + kk * 64 + tx * 4];
            #pragma unroll
            for (int i = 0; i < 4; i++) {
                float a = fsm[FS_P + (ty * 4 + i) * 72 + kk];
                #pragma unroll
                for (int j = 0; j < 4; j++) acc[i][j] += a * bb[j];
            }
        }
    }

    // global-key column
    #pragma unroll
    for (int i = 0; i < 4; i++) {
        int row = ty * 4 + i;
        float sg = 0.f;
        #pragma unroll
        for (int e = 0; e < 4; e++) {
            int d = tx * 4 + e;
            sg += fsm[FS_Q + d * 64 + row] * fsm[FS_K0 + d];
        }
        #pragma unroll
        for (int o = 1; o < 16; o <<= 1)
            sg += __shfl_xor_sync(0xffffffffu, sg, o);
        if (am0 <= 0) sg = CNEG;
        float nm = fmaxf(mst[i], sg);
        float alpha = __expf(mst[i] - nm);
        float pg = __expf(sg - nm);
        float l = lst[i] * alpha + pg;
        float inv = 1.0f / l;
        int sgl = base_s + row;
        float o4[4];
        #pragma unroll
        for (int j = 0; j < 4; j++) {
            int d = tx * 4 + j;
            o4[j] = (acc[i][j] * alpha + pg * fsm[FS_V0 + d]) * inv;
        }
        *(float4*)&out[((size_t)(b * CS + sgl)) * CDM + h * 64 + tx * 4] =
            make_float4(o4[0], o4[1], o4[2], o4[3]);
    }
}

// ================= small kernels =================
__device__ __forceinline__ float block_reduce_sum256(float v, float* red) {
    int tid = threadIdx.x;
    red[tid] = v; __syncthreads();
    #pragma unroll
    for (int o = 128; o > 0; o >>= 1) {
        if (tid < o) red[tid] += red[tid + o];
        __syncthreads();
    }
    float r = red[0]; __syncthreads();
    return r;
}

__global__ void embed_ln_kernel(const int* __restrict__ ids,
                                const float* __restrict__ we,
                                const float* __restrict__ pe,
                                const float* __restrict__ gam,
                                const float* __restrict__ bet,
                                float* __restrict__ x) {
    __shared__ float red[256];
    int row = blockIdx.x;
    int s = row % CS;
    int id = ids[row];
    int tid = threadIdx.x;
    const float* wp = we + (size_t)id * CDM;
    const float* pp = pe + (size_t)s * CDM;
    float e[3];
    float sm = 0.f;
    #pragma unroll
    for (int i = 0; i < 3; i++) { int d = tid + i * 256; e[i] = wp[d] + pp[d]; sm += e[i]; }
    float mean = block_reduce_sum256(sm, red) * (1.0f / CDM);
    float vs = 0.f;
    #pragma unroll
    for (int i = 0; i < 3; i++) { float t = e[i] - mean; vs += t * t; }
    float var = block_reduce_sum256(vs, red) * (1.0f / CDM);
    float inv = rsqrtf(var + 1e-5f);
    float* xr = x + (size_t)row * CDM;
    #pragma unroll
    for (int i = 0; i < 3; i++) { int d = tid + i * 256; xr[d] = (e[i] - mean) * inv * gam[d] + bet[d]; }
}

__global__ void add_ln_kernel(float* __restrict__ x,
                              const float* __restrict__ y,
                              const float* __restrict__ gam,
                              const float* __restrict__ bet) {
    __shared__ float red[256];
    int row = blockIdx.x;
    int tid = threadIdx.x;
    float* xr = x + (size_t)row * CDM;
    const float* yr = y + (size_t)row * CDM;
    float e[3];
    float sm = 0.f;
    #pragma unroll
    for (int i = 0; i < 3; i++) { int d = tid + i * 256; e[i] = xr[d] + yr[d]; sm += e[i]; }
    float mean = block_reduce_sum256(sm, red) * (1.0f / CDM);
    float vs = 0.f;
    #pragma unroll
    for (int i = 0; i < 3; i++) { float t = e[i] - mean; vs += t * t; }
    float var = block_reduce_sum256(vs, red) * (1.0f / CDM);
    float inv = rsqrtf(var + 1e-5f);
    #pragma unroll
    for (int i = 0; i < 3; i++) { int d = tid + i * 256; xr[d] = (e[i] - mean) * inv * gam[d] + bet[d]; }
}

__global__ void qg_kernel(const float* __restrict__ x,
                          const float* __restrict__ Wqg,
                          const float* __restrict__ bqg,
                          float* __restrict__ qg) {
    int nidx = blockIdx.x * 256 + threadIdx.x;
    int b = blockIdx.y;
    const float* xr = x + (size_t)(b * CS) * CDM;
    float acc = bqg[nidx];
    for (int kk = 0; kk < CDM; kk++)
        acc += xr[kk] * Wqg[(size_t)kk * CDM + nidx];
    qg[b * CDM + nidx] = acc * CSCALE;
}

__global__ void global_attn_kernel(const float* __restrict__ qg,
                                   const float* __restrict__ kg,
                                   const float* __restrict__ vg,
                                   const int* __restrict__ am,
                                   float* __restrict__ out) {
    __shared__ float scs[CS];
    __shared__ float red[256];
    __shared__ float qs[64];
    int h = blockIdx.x, b = blockIdx.y;
    int tid = threadIdx.x;
    if (tid < 64) qs[tid] = qg[b * CDM + h * 64 + tid];
    __syncthreads();

    float mx = -1e30f;
    for (int s = tid; s < CS; s += 256) {
        const float* kp = &kg[((size_t)(b * CS + s)) * CDM + h * 64];
        float dd = 0.f;
        #pragma unroll
        for (int e = 0; e < 64; e++) dd += qs[e] * kp[e];
        if (am[b * CS + s] <= 0) dd = CNEG;
        scs[s] = dd;
        mx = fmaxf(mx, dd);
    }
    red[tid] = mx; __syncthreads();
    #pragma unroll
    for (int o = 128; o > 0; o >>= 1) {
        if (tid < o) red[tid] = fmaxf(red[tid], red[tid + o]);
        __syncthreads();
    }
    mx = red[0]; __syncthreads();

    float sm = 0.f;
    for (int s = tid; s < CS; s += 256) {
        float e = __expf(scs[s] - mx);
        scs[s] = e; sm += e;
    }
    float tot = block_reduce_sum256(sm, red);
    float inv = 1.0f / tot;
    __syncthreads();

    int d = tid & 63, sl = tid >> 6;
    float acc = 0.f;
    for (int s = sl * 1024; s < (sl + 1) * 1024; s++)
        acc += scs[s] * vg[((size_t)(b * CS + s)) * CDM + h * 64 + d];
    red[tid] = acc; __syncthreads();
    if (sl == 0) {
        float t = red[d] + red[64 + d] + red[128 + d] + red[192 + d];
        out[((size_t)(b * CS)) * CDM + h * 64 + d] = t * inv;
    }
}

__global__ void cls_kernel(const float* __restrict__ x,
                           const float* __restrict__ Wc,
                           const float* __restrict__ bc,
                           float* __restrict__ out) {
    __shared__ float red[256];
    int b = blockIdx.x >> 1, c = blockIdx.x & 1;
    int tid = threadIdx.x;
    const float* xr = x + (size_t)(b * CS) * CDM;
    float acc = 0.f;
    for (int d = tid; d < CDM; d += 256) acc += xr[d] * Wc[d * 2 + c];
    float tot = block_reduce_sum256(acc, red);
    if (tid == 0) out[b * 2 + c] = tot + bc[c];
}

// ================= launch =================
extern "C" void kernel_launch(void* const* d_in, const int* in_sizes, int n_in,
                              void* d_out, int out_size) {
    const int*   ids  = (const int*)d_in[0];
    const int*   am   = (const int*)d_in[1];
    const float* we   = (const float*)d_in[2];
    const float* pe   = (const float*)d_in[3];
    const float* lnes = (const float*)d_in[4];
    const float* lneb = (const float*)d_in[5];
    const float* Wq   = (const float*)d_in[6];
    const float* bq   = (const float*)d_in[7];
    const float* Wk   = (const float*)d_in[8];
    const float* bk   = (const float*)d_in[9];
    const float* Wv   = (const float*)d_in[10];
    const float* bv   = (const float*)d_in[11];
    const float* Wqg  = (const float*)d_in[12];
    const float* bqg  = (const float*)d_in[13];
    const float* Wkg  = (const float*)d_in[14];
    const float* bkg  = (const float*)d_in[15];
    const float* Wvg  = (const float*)d_in[16];
    const float* bvg  = (const float*)d_in[17];
    const float* Wo   = (const float*)d_in[18];
    const float* bo   = (const float*)d_in[19];
    const float* ln1s = (const float*)d_in[20];
    const float* ln1b = (const float*)d_in[21];
    const float* W1   = (const float*)d_in[22];
    const float* b1   = (const float*)d_in[23];
    const float* W2   = (const float*)d_in[24];
    const float* b2   = (const float*)d_in[25];
    const float* ln2s = (const float*)d_in[26];
    const float* ln2b = (const float*)d_in[27];
    const float* Wcls = (const float*)d_in[28];
    const float* bcls = (const float*)d_in[29];
    float* out = (float*)d_out;

    float *xp, *qp, *kp, *vp, *ap, *h1p, *qgp;
    __nv_bfloat16 *xbp, *hbp, *wbp;
    cudaGetSymbolAddress((void**)&xp,  g_x);
    cudaGetSymbolAddress((void**)&qp,  g_q);
    cudaGetSymbolAddress((void**)&kp,  g_k);
    cudaGetSymbolAddress((void**)&vp,  g_v);
    cudaGetSymbolAddress((void**)&ap,  g_attn);
    cudaGetSymbolAddress((void**)&h1p, g_h1);
    cudaGetSymbolAddress((void**)&qgp, g_qg);
    cudaGetSymbolAddress((void**)&xbp, g_xb);
    cudaGetSymbolAddress((void**)&hbp, g_hb);
    cudaGetSymbolAddress((void**)&wbp, g_wb);

    cudaFuncSetAttribute(gemm_mma_kernel, cudaFuncAttributeMaxDynamicSharedMemorySize, GSM_TOT);
    cudaFuncSetAttribute(flash_band_kernel, cudaFuncAttributeMaxDynamicSharedMemorySize, FS_TOT);

    embed_ln_kernel<<<MROWS, 256>>>(ids, we, pe, lnes, lneb, xp);

    dim3 g_dm(CDM / 128, MROWS / 128);    // (6, 64)
    dim3 g_ff(CDFF / 128, MROWS / 128);   // (24, 64)
    dim3 wt_dm(CDM / 32, CDM / 32);
    dim3 wt_b(32, 8);
    int actK  = MROWS * CDM / 256;
    int actKf = MROWS * CDFF / 256;

    for (int l = 0; l < CL; l++) {
        size_t woff = (size_t)l * CDM * CDM;
        size_t boff = (size_t)l * CDM;
        size_t w1off = (size_t)l * CDM * CDFF;
        size_t b1off = (size_t)l * CDFF;
        size_t w2off = (size_t)l * CDFF * CDM;

        split_act_kernel<<<actK, 256>>>(xp, xbp, CDM);

        split_wt_kernel<<<wt_dm, wt_b>>>(Wq + woff, wbp, CDM, CDM);
        gemm_mma_kernel<<<g_dm, 256, GSM_TOT>>>(xbp, wbp, bq + boff, qp, 3 * CDM, CDM, 0);
        split_wt_kernel<<<wt_dm, wt_b>>>(Wk + woff, wbp, CDM, CDM);
        gemm_mma_kernel<<<g_dm, 256, GSM_TOT>>>(xbp, wbp, bk + boff, kp, 3 * CDM, CDM, 0);
        split_wt_kernel<<<wt_dm, wt_b>>>(Wv + woff, wbp, CDM, CDM);
        gemm_mma_kernel<<<g_dm, 256, GSM_TOT>>>(xbp, wbp, bv + boff, vp, 3 * CDM, CDM, 0);

        flash_band_kernel<<<dim3(4, CB * CH * CNB), 256, FS_TOT>>>(qp, kp, vp, am, ap);

        qg_kernel<<<dim3(CDM / 256, CB), 256>>>(xp, Wqg + woff, bqg + boff, qgp);
        split_wt_kernel<<<wt_dm, wt_b>>>(Wkg + woff, wbp, CDM, CDM);
        gemm_mma_kernel<<<g_dm, 256, GSM_TOT>>>(xbp, wbp, bkg + boff, kp, 3 * CDM, CDM, 0);
        split_wt_kernel<<<wt_dm, wt_b>>>(Wvg + woff, wbp, CDM, CDM);
        gemm_mma_kernel<<<g_dm, 256, GSM_TOT>>>(xbp, wbp, bvg + boff, vp, 3 * CDM, CDM, 0);
        global_attn_kernel<<<dim3(CH, CB), 256>>>(qgp, kp, vp, am, ap);

        split_act_kernel<<<actK, 256>>>(ap, xbp, CDM);
        split_wt_kernel<<<wt_dm, wt_b>>>(Wo + woff, wbp, CDM, CDM);
        gemm_mma_kernel<<<g_dm, 256, GSM_TOT>>>(xbp, wbp, bo + boff, qp, 3 * CDM, CDM, 0);
        add_ln_kernel<<<MROWS, 256>>>(xp, qp, ln1s + boff, ln1b + boff);

        split_act_kernel<<<actK, 256>>>(xp, xbp, CDM);
        split_wt_kernel<<<dim3(CDFF / 32, CDM / 32), wt_b>>>(W1 + w1off, wbp, CDM, CDFF);
        gemm_mma_kernel<<<g_ff, 256, GSM_TOT>>>(xbp, wbp, b1 + b1off, h1p, 3 * CDM, CDFF, 1);

        split_act_kernel<<<actKf, 256>>>(h1p, hbp, CDFF);
        split_wt_kernel<<<dim3(CDM / 32, CDFF / 32), wt_b>>>(W2 + w2off, wbp, CDFF, CDM);
        gemm_mma_kernel<<<g_dm, 256, GSM_TOT>>>(hbp, wbp, b2 + boff, qp, 3 * CDFF, CDM, 0);
        add_ln_kernel<<<MROWS, 256>>>(xp, qp, ln2s + boff, ln2b + boff);
    }

    cls_kernel<<<4, 256>>>(xp, Wcls, bcls, out);
}

// round 6
// speedup vs baseline: 1.8375x; 1.0404x over previous
#include <cuda_runtime.h>
#include <cuda_bf16.h>
#include <math.h>
#include <stdint.h>

// ---------------- problem constants ----------------
#define CB   2
#define CS   4096
#define CH   12
#define CD   64
#define CW   256
#define CDM  768
#define CDFF 3072
#define CNB  16
#define CL   2
#define CNEG (-1000000000.0f)
#define CSCALE 0.125f

#define MROWS (CB*CS)    // 8192
#define QKV_S 2304       // q|k|v column stride
#define GKV_S 1536       // kg|vg column stride

// ---------------- scratch ----------------
__device__ float g_x   [MROWS*CDM];
__device__ float g_y   [MROWS*CDM];
__device__ float g_attn[MROWS*CDM];
__device__ float g_qkv [(size_t)MROWS*QKV_S];
__device__ float g_gkv [(size_t)MROWS*GKV_S];
__device__ float g_qg  [CB*CDM];
__device__ float g_bias[QKV_S];
// bf16 split buffers (K' = 3K: A' = [hi|lo|hi], B' = [hi|hi|lo])
__device__ __nv_bfloat16 g_xb[(size_t)MROWS*3*CDM];
__device__ __nv_bfloat16 g_hb[(size_t)MROWS*3*CDFF];
__device__ __nv_bfloat16 g_wb[(size_t)3*CDFF*CDM];

// ---------------- helpers ----------------
__device__ __forceinline__ float gelu_tanh(float x) {
    float x3 = x * x * x;
    return 0.5f * x * (1.0f + tanhf(0.7978845608028654f * (x + 0.044715f * x3)));
}
__device__ __forceinline__ uint32_t smem_u32(const void* p) {
    uint32_t a;
    asm("{ .reg .u64 t; cvta.to.shared.u64 t, %1; cvt.u32.u64 %0, t; }" : "=r"(a) : "l"(p));
    return a;
}
__device__ __forceinline__ void split_write(__nv_bfloat16* dst, size_t ro, int K, int k, float v) {
    __nv_bfloat16 hi = __float2bfloat16_rn(v);
    __nv_bfloat16 lo = __float2bfloat16_rn(v - __bfloat162float(hi));
    dst[ro + k] = hi;
    dst[ro + K + k] = lo;
    dst[ro + 2 * K + k] = hi;
}

// ================= split/convert kernels =================
__global__ void split_act_kernel(const float* __restrict__ A,
                                 __nv_bfloat16* __restrict__ Ap, int K) {
    int idx = blockIdx.x * 256 + threadIdx.x;
    int m = idx / K, k = idx - m * K;
    split_write(Ap, (size_t)m * (3 * K), K, k, A[idx]);
}

__global__ void split_wt_kernel(const float* __restrict__ W,
                                __nv_bfloat16* __restrict__ Wt, int K, int N) {
    __shared__ float t[32][33];
    int n0 = blockIdx.x * 32, k0 = blockIdx.y * 32;
    int tx = threadIdx.x, ty = threadIdx.y;   // 32 x 8
    #pragma unroll
    for (int r = 0; r < 4; r++) {
        int k = k0 + ty + r * 8;
        t[ty + r * 8][tx] = W[(size_t)k * N + n0 + tx];
    }
    __syncthreads();
    #pragma unroll
    for (int r = 0; r < 4; r++) {
        int n = n0 + ty + r * 8;
        int k = k0 + tx;
        float a = t[tx][ty + r * 8];
        __nv_bfloat16 hi = __float2bfloat16_rn(a);
        __nv_bfloat16 lo = __float2bfloat16_rn(a - __bfloat162float(hi));
        size_t ro = (size_t)n * (3 * K);
        Wt[ro + k] = hi;
        Wt[ro + K + k] = hi;
        Wt[ro + 2 * K + k] = lo;
    }
}

// pack up to 3 x 768-wide bias vectors; grid sized to total width / 256
__global__ void pack_bias_kernel(float* __restrict__ dst,
                                 const float* __restrict__ s0,
                                 const float* __restrict__ s1,
                                 const float* __restrict__ s2) {
    int i = blockIdx.x * 256 + threadIdx.x;
    int seg = i >> 9;                  // not used; compute via /768 below
    (void)seg;
    int s = i / 768, r = i - s * 768;
    const float* p = (s == 0) ? s0 : (s == 1 ? s1 : s2);
    dst[i] = p[r];
}

// ================= warp-MMA bf16 GEMM (4-stage cp.async pipeline) ==========
#define AB_BYTES 10240          // 128 rows * 80B
#define BUF_BYTES (2*AB_BYTES)  // A + B per stage
#define GSM_TOT (4*BUF_BYTES)   // 81920

__device__ __forceinline__ void ldm_x4(uint32_t addr, uint32_t& r0, uint32_t& r1,
                                       uint32_t& r2, uint32_t& r3) {
    asm volatile("ldmatrix.sync.aligned.m8n8.x4.shared.b16 {%0,%1,%2,%3}, [%4];"
        : "=r"(r0), "=r"(r1), "=r"(r2), "=r"(r3) : "r"(addr));
}
__device__ __forceinline__ void mma_bf16(float* c, const uint32_t* a, const uint32_t* b) {
    asm volatile("mma.sync.aligned.m16n8k16.row.col.f32.bf16.bf16.f32 "
        "{%0,%1,%2,%3}, {%4,%5,%6,%7}, {%8,%9}, {%0,%1,%2,%3};"
        : "+f"(c[0]), "+f"(c[1]), "+f"(c[2]), "+f"(c[3])
        : "r"(a[0]), "r"(a[1]), "r"(a[2]), "r"(a[3]), "r"(b[0]), "r"(b[1]));
}

// mode 0: Cf = acc+bias ; mode 1: Cf = gelu(acc+bias) ;
// mode 2: Cb = bf16-split(gelu(acc+bias)), layout [row][3N]
__global__ __launch_bounds__(256)
void gemm_mma_kernel(const __nv_bfloat16* __restrict__ A,
                     const __nv_bfloat16* __restrict__ Bt,
                     const float* __restrict__ bias,
                     float* __restrict__ Cf,
                     __nv_bfloat16* __restrict__ Cb,
                     int Kp, int N, int mode) {
    extern __shared__ __align__(1024) char smem[];
    uint32_t sb = smem_u32(smem);
    int tid = threadIdx.x;
    int wid = tid >> 5, lane = tid & 31;
    int m0 = blockIdx.y * 128, n0 = blockIdx.x * 128;
    int warp_m = (wid & 1) * 64;
    int warp_n = (wid >> 1) * 32;
    int NC = Kp / 32;

    const __nv_bfloat16* Ag = A  + (size_t)m0 * Kp;
    const __nv_bfloat16* Bg = Bt + (size_t)n0 * Kp;

    float acc[4][4][4];
    #pragma unroll
    for (int i = 0; i < 4; i++)
        #pragma unroll
        for (int j = 0; j < 4; j++)
            #pragma unroll
            for (int r = 0; r < 4; r++) acc[i][j][r] = 0.f;

    auto load_tile = [&](int c, int bf) {
        uint32_t abase = sb + bf * BUF_BYTES;
        uint32_t bbase = abase + AB_BYTES;
        const __nv_bfloat16* Ac = Ag + (size_t)c * 32;
        const __nv_bfloat16* Bc = Bg + (size_t)c * 32;
        #pragma unroll
        for (int i = 0; i < 2; i++) {
            int chunk = tid * 2 + i;            // 0..511
            int r = chunk >> 2, cc = (chunk & 3) * 8;
            uint32_t ad = abase + r * 80 + cc * 2;
            const void* as = Ac + (size_t)r * Kp + cc;
            asm volatile("cp.async.cg.shared.global [%0], [%1], 16;" :: "r"(ad), "l"(as));
            uint32_t bd = bbase + r * 80 + cc * 2;
            const void* bs = Bc + (size_t)r * Kp + cc;
            asm volatile("cp.async.cg.shared.global [%0], [%1], 16;" :: "r"(bd), "l"(bs));
        }
    };

    load_tile(0, 0);
    asm volatile("cp.async.commit_group;" ::: "memory");
    load_tile(1, 1);
    asm volatile("cp.async.commit_group;" ::: "memory");
    load_tile(2, 2);
    asm volatile("cp.async.commit_group;" ::: "memory");

    int bf = 0;
    for (int c = 0; c < NC; c++) {
        asm volatile("cp.async.wait_group 2;" ::: "memory");
        __syncthreads();
        if (c + 3 < NC) load_tile(c + 3, (bf + 3) & 3);
        asm volatile("cp.async.commit_group;" ::: "memory");

        uint32_t abase = sb + bf * BUF_BYTES;
        uint32_t bbase = abase + AB_BYTES;
        int rsel = lane & 15, hsel = (lane >> 4) * 16;

        #pragma unroll
        for (int ks = 0; ks < 2; ks++) {
            uint32_t a[4][4], b[4][2];
            #pragma unroll
            for (int mi = 0; mi < 4; mi++) {
                uint32_t ad = abase + (warp_m + mi * 16 + rsel) * 80 + ks * 32 + hsel;
                ldm_x4(ad, a[mi][0], a[mi][1], a[mi][2], a[mi][3]);
            }
            #pragma unroll
            for (int np = 0; np < 2; np++) {
                uint32_t r0, r1, r2, r3;
                uint32_t bd = bbase + (warp_n + np * 16 + rsel) * 80 + ks * 32 + hsel;
                ldm_x4(bd, r0, r1, r2, r3);
                b[np * 2 + 0][0] = r0; b[np * 2 + 0][1] = r2;
                b[np * 2 + 1][0] = r1; b[np * 2 + 1][1] = r3;
            }
            #pragma unroll
            for (int mi = 0; mi < 4; mi++)
                #pragma unroll
                for (int nj = 0; nj < 4; nj++)
                    mma_bf16(acc[mi][nj], a[mi], b[nj]);
        }
        bf = (bf + 1) & 3;
    }

    // epilogue
    int g = lane >> 2, t = lane & 3;
    #pragma unroll
    for (int mi = 0; mi < 4; mi++) {
        int row0 = m0 + warp_m + mi * 16 + g;
        #pragma unroll
        for (int nj = 0; nj < 4; nj++) {
            int col = n0 + warp_n + nj * 8 + t * 2;
            float bx = bias[col], by = bias[col + 1];
            float v0 = acc[mi][nj][0] + bx, v1 = acc[mi][nj][1] + by;
            float v2 = acc[mi][nj][2] + bx, v3 = acc[mi][nj][3] + by;
            if (mode >= 1) { v0 = gelu_tanh(v0); v1 = gelu_tanh(v1); v2 = gelu_tanh(v2); v3 = gelu_tanh(v3); }
            if (mode == 2) {
                #pragma unroll
                for (int rr = 0; rr < 2; rr++) {
                    int row = row0 + rr * 8;
                    float a0 = rr ? v2 : v0, a1 = rr ? v3 : v1;
                    __nv_bfloat16 h0 = __float2bfloat16_rn(a0);
                    __nv_bfloat16 l0 = __float2bfloat16_rn(a0 - __bfloat162float(h0));
                    __nv_bfloat16 h1 = __float2bfloat16_rn(a1);
                    __nv_bfloat16 l1 = __float2bfloat16_rn(a1 - __bfloat162float(h1));
                    size_t ro = (size_t)row * (3 * N);
                    *(__nv_bfloat162*)&Cb[ro + col]         = __halves2bfloat162(h0, h1);
                    *(__nv_bfloat162*)&Cb[ro + N + col]     = __halves2bfloat162(l0, l1);
                    *(__nv_bfloat162*)&Cb[ro + 2 * N + col] = __halves2bfloat162(h0, h1);
                }
            } else {
                *(float2*)&Cf[(size_t)row0 * N + col]       = make_float2(v0, v1);
                *(float2*)&Cf[(size_t)(row0 + 8) * N + col] = make_float2(v2, v3);
            }
        }
    }
}

// ================= fused flash band attention =================
#define FS_Q  0
#define FS_K  4096
#define FS_V  8192
#define FS_P  12288      // Ps[64][72]
#define FS_K0 16896
#define FS_V0 16960
#define FS_TOT ((16960 + 64) * 4)

__global__ __launch_bounds__(256)
void flash_band_kernel(const float* __restrict__ qkv,
                       const int* __restrict__ am,
                       float* __restrict__ out) {
    extern __shared__ float fsm[];
    int z = blockIdx.y;
    int n = z % CNB;
    int h = (z / CNB) % CH;
    int b = z / (CNB * CH);
    int qt = blockIdx.x;
    int tid = threadIdx.x;
    int tx = tid & 15, ty = tid >> 4;

    int base_s    = n * CW + qt * 64;
    int base_kpos = n * CW - CW;

    #pragma unroll
    for (int i = 0; i < 4; i++) {
        int sid = tid + i * 256;
        int r = sid >> 4, c4 = (sid & 15) << 2;
        float4 vq = *(const float4*)&qkv[((size_t)(b * CS + base_s + r)) * QKV_S + h * 64 + c4];
        fsm[FS_Q + (c4 + 0) * 64 + r] = vq.x * CSCALE;
        fsm[FS_Q + (c4 + 1) * 64 + r] = vq.y * CSCALE;
        fsm[FS_Q + (c4 + 2) * 64 + r] = vq.z * CSCALE;
        fsm[FS_Q + (c4 + 3) * 64 + r] = vq.w * CSCALE;
    }
    if (tid < 64) {
        fsm[FS_K0 + tid] = qkv[((size_t)(b * CS)) * QKV_S + 768 + h * 64 + tid];
        fsm[FS_V0 + tid] = qkv[((size_t)(b * CS)) * QKV_S + 1536 + h * 64 + tid];
    }

    float mst[4], lst[4], acc[4][4];
    #pragma unroll
    for (int i = 0; i < 4; i++) {
        mst[i] = -1e30f; lst[i] = 0.f;
        #pragma unroll
        for (int j = 0; j < 4; j++) acc[i][j] = 0.f;
    }
    int am0 = am[b * CS];

    for (int kc = 0; kc < 12; kc++) {
        __syncthreads();
        #pragma unroll
        for (int i = 0; i < 4; i++) {
            int sid = tid + i * 256;
            int r = sid >> 4, c4 = (sid & 15) << 2;
            int kpos = base_kpos + kc * 64 + r;
            float4 vk = make_float4(0.f, 0.f, 0.f, 0.f);
            float4 vv = make_float4(0.f, 0.f, 0.f, 0.f);
            if (kpos >= 0 && kpos < CS) {
                size_t rb = ((size_t)(b * CS + kpos)) * QKV_S + h * 64 + c4;
                vk = *(const float4*)&qkv[rb + 768];
                vv = *(const float4*)&qkv[rb + 1536];
            }
            fsm[FS_K + (c4 + 0) * 64 + r] = vk.x;
            fsm[FS_K + (c4 + 1) * 64 + r] = vk.y;
            fsm[FS_K + (c4 + 2) * 64 + r] = vk.z;
            fsm[FS_K + (c4 + 3) * 64 + r] = vk.w;
            *(float4*)&fsm[FS_V + r * 64 + c4] = vv;
        }
        __syncthreads();

        float s[4][4];
        #pragma unroll
        for (int i = 0; i < 4; i++)
            #pragma unroll
            for (int j = 0; j < 4; j++) s[i][j] = 0.f;
        #pragma unroll 8
        for (int kk = 0; kk < 64; kk++) {
            float a[4], bb[4];
            *(float4*)a  = *(const float4*)&fsm[FS_Q + kk * 64 + ty * 4];
            *(float4*)bb = *(const float4*)&fsm[FS_K + kk * 64 + tx * 4];
            #pragma unroll
            for (int i = 0; i < 4; i++)
                #pragma unroll
                for (int j = 0; j < 4; j++)
                    s[i][j] += a[i] * bb[j];
        }

        #pragma unroll
        for (int i = 0; i < 4; i++) {
            int qi = qt * 64 + ty * 4 + i;
            #pragma unroll
            for (int j = 0; j < 4; j++) {
                int kj = kc * 64 + tx * 4 + j;
                int kpos = base_kpos + kj;
                bool ok = (kj >= qi) && (kj <= qi + 2 * CW) &&
                          (kpos >= 0) && (kpos < CS) && (kpos != 0) &&
                          (am[b * CS + (kpos & (CS - 1))] > 0);
                if (!ok) s[i][j] = CNEG;
            }
        }

        #pragma unroll
        for (int i = 0; i < 4; i++) {
            float cm = fmaxf(fmaxf(s[i][0], s[i][1]), fmaxf(s[i][2], s[i][3]));
            #pragma unroll
            for (int o = 1; o < 16; o <<= 1)
                cm = fmaxf(cm, __shfl_xor_sync(0xffffffffu, cm, o));
            float nm = fmaxf(mst[i], cm);
            float alpha = __expf(mst[i] - nm);
            mst[i] = nm;
            float rs = 0.f;
            #pragma unroll
            for (int j = 0; j < 4; j++) {
                s[i][j] = __expf(s[i][j] - nm);
                rs += s[i][j];
            }
            #pragma unroll
            for (int o = 1; o < 16; o <<= 1)
                rs += __shfl_xor_sync(0xffffffffu, rs, o);
            lst[i] = lst[i] * alpha + rs;
            #pragma unroll
            for (int j = 0; j < 4; j++) acc[i][j] *= alpha;
            int qi = ty * 4 + i;
            *(float4*)&fsm[FS_P + qi * 72 + tx * 4] = make_float4(s[i][0], s[i][1], s[i][2], s[i][3]);
        }
        __syncthreads();

        #pragma unroll 4
        for (int kk = 0; kk < 64; kk++) {
            float bb[4];
            *(float4*)bb = *(const float4*)&fsm[FS_V + kk * 64 + tx * 4];
            #pragma unroll
            for (int i = 0; i < 4; i++) {
                float a = fsm[FS_P + (ty * 4 + i) * 72 + kk];
                #pragma unroll
                for (int j = 0; j < 4; j++) acc[i][j] += a * bb[j];
            }
        }
    }

    #pragma unroll
    for (int i = 0; i < 4; i++) {
        int row = ty * 4 + i;
        float sg = 0.f;
        #pragma unroll
        for (int e = 0; e < 4; e++) {
            int d = tx * 4 + e;
            sg += fsm[FS_Q + d * 64 + row] * fsm[FS_K0 + d];
        }
        #pragma unroll
        for (int o = 1; o < 16; o <<= 1)
            sg += __shfl_xor_sync(0xffffffffu, sg, o);
        if (am0 <= 0) sg = CNEG;
        float nm = fmaxf(mst[i], sg);
        float alpha = __expf(mst[i] - nm);
        float pg = __expf(sg - nm);
        float l = lst[i] * alpha + pg;
        float inv = 1.0f / l;
        int sgl = base_s + row;
        float o4[4];
        #pragma unroll
        for (int j = 0; j < 4; j++) {
            int d = tx * 4 + j;
            o4[j] = (acc[i][j] * alpha + pg * fsm[FS_V0 + d]) * inv;
        }
        *(float4*)&out[((size_t)(b * CS + sgl)) * CDM + h * 64 + tx * 4] =
            make_float4(o4[0], o4[1], o4[2], o4[3]);
    }
}

// ================= small kernels =================
__device__ __forceinline__ float block_reduce_sum256(float v, float* red) {
    int tid = threadIdx.x;
    red[tid] = v; __syncthreads();
    #pragma unroll
    for (int o = 128; o > 0; o >>= 1) {
        if (tid < o) red[tid] += red[tid + o];
        __syncthreads();
    }
    float r = red[0]; __syncthreads();
    return r;
}

__global__ void embed_ln_kernel(const int* __restrict__ ids,
                                const float* __restrict__ we,
                                const float* __restrict__ pe,
                                const float* __restrict__ gam,
                                const float* __restrict__ bet,
                                float* __restrict__ x,
                                __nv_bfloat16* __restrict__ xb) {
    __shared__ float red[256];
    int row = blockIdx.x;
    int s = row % CS;
    int id = ids[row];
    int tid = threadIdx.x;
    const float* wp = we + (size_t)id * CDM;
    const float* pp = pe + (size_t)s * CDM;
    float e[3];
    float sm = 0.f;
    #pragma unroll
    for (int i = 0; i < 3; i++) { int d = tid + i * 256; e[i] = wp[d] + pp[d]; sm += e[i]; }
    float mean = block_reduce_sum256(sm, red) * (1.0f / CDM);
    float vs = 0.f;
    #pragma unroll
    for (int i = 0; i < 3; i++) { float t = e[i] - mean; vs += t * t; }
    float var = block_reduce_sum256(vs, red) * (1.0f / CDM);
    float inv = rsqrtf(var + 1e-5f);
    float* xr = x + (size_t)row * CDM;
    size_t ro = (size_t)row * (3 * CDM);
    #pragma unroll
    for (int i = 0; i < 3; i++) {
        int d = tid + i * 256;
        float val = (e[i] - mean) * inv * gam[d] + bet[d];
        xr[d] = val;
        split_write(xb, ro, CDM, d, val);
    }
}

__global__ void add_ln_kernel(float* __restrict__ x,
                              const float* __restrict__ y,
                              const float* __restrict__ gam,
                              const float* __restrict__ bet,
                              __nv_bfloat16* __restrict__ xb) {
    __shared__ float red[256];
    int row = blockIdx.x;
    int tid = threadIdx.x;
    float* xr = x + (size_t)row * CDM;
    const float* yr = y + (size_t)row * CDM;
    float e[3];
    float sm = 0.f;
    #pragma unroll
    for (int i = 0; i < 3; i++) { int d = tid + i * 256; e[i] = xr[d] + yr[d]; sm += e[i]; }
    float mean = block_reduce_sum256(sm, red) * (1.0f / CDM);
    float vs = 0.f;
    #pragma unroll
    for (int i = 0; i < 3; i++) { float t = e[i] - mean; vs += t * t; }
    float var = block_reduce_sum256(vs, red) * (1.0f / CDM);
    float inv = rsqrtf(var + 1e-5f);
    size_t ro = (size_t)row * (3 * CDM);
    #pragma unroll
    for (int i = 0; i < 3; i++) {
        int d = tid + i * 256;
        float val = (e[i] - mean) * inv * gam[d] + bet[d];
        xr[d] = val;
        split_write(xb, ro, CDM, d, val);
    }
}

__global__ void qg_kernel(const float* __restrict__ x,
                          const float* __restrict__ Wqg,
                          const float* __restrict__ bqg,
                          float* __restrict__ qg) {
    int nidx = blockIdx.x * 256 + threadIdx.x;
    int b = blockIdx.y;
    const float* xr = x + (size_t)(b * CS) * CDM;
    float acc = bqg[nidx];
    for (int kk = 0; kk < CDM; kk++)
        acc += xr[kk] * Wqg[(size_t)kk * CDM + nidx];
    qg[b * CDM + nidx] = acc * CSCALE;
}

__global__ void global_attn_kernel(const float* __restrict__ qg,
                                   const float* __restrict__ gkv,
                                   const int* __restrict__ am,
                                   float* __restrict__ out) {
    __shared__ float scs[CS];
    __shared__ float red[256];
    __shared__ float qs[64];
    int h = blockIdx.x, b = blockIdx.y;
    int tid = threadIdx.x;
    if (tid < 64) qs[tid] = qg[b * CDM + h * 64 + tid];
    __syncthreads();

    float mx = -1e30f;
    for (int s = tid; s < CS; s += 256) {
        const float* kp = &gkv[((size_t)(b * CS + s)) * GKV_S + h * 64];
        float dd = 0.f;
        #pragma unroll
        for (int e = 0; e < 64; e++) dd += qs[e] * kp[e];
        if (am[b * CS + s] <= 0) dd = CNEG;
        scs[s] = dd;
        mx = fmaxf(mx, dd);
    }
    red[tid] = mx; __syncthreads();
    #pragma unroll
    for (int o = 128; o > 0; o >>= 1) {
        if (tid < o) red[tid] = fmaxf(red[tid], red[tid + o]);
        __syncthreads();
    }
    mx = red[0]; __syncthreads();

    float sm = 0.f;
    for (int s = tid; s < CS; s += 256) {
        float e = __expf(scs[s] - mx);
        scs[s] = e; sm += e;
    }
    float tot = block_reduce_sum256(sm, red);
    float inv = 1.0f / tot;
    __syncthreads();

    int d = tid & 63, sl = tid >> 6;
    float acc = 0.f;
    for (int s = sl * 1024; s < (sl + 1) * 1024; s++)
        acc += scs[s] * gkv[((size_t)(b * CS + s)) * GKV_S + 768 + h * 64 + d];
    red[tid] = acc; __syncthreads();
    if (sl == 0) {
        float t = red[d] + red[64 + d] + red[128 + d] + red[192 + d];
        out[((size_t)(b * CS)) * CDM + h * 64 + d] = t * inv;
    }
}

__global__ void cls_kernel(const float* __restrict__ x,
                           const float* __restrict__ Wc,
                           const float* __restrict__ bc,
                           float* __restrict__ out) {
    __shared__ float red[256];
    int b = blockIdx.x >> 1, c = blockIdx.x & 1;
    int tid = threadIdx.x;
    const float* xr = x + (size_t)(b * CS) * CDM;
    float acc = 0.f;
    for (int d = tid; d < CDM; d += 256) acc += xr[d] * Wc[d * 2 + c];
    float tot = block_reduce_sum256(acc, red);
    if (tid == 0) out[b * 2 + c] = tot + bc[c];
}

// ================= launch =================
extern "C" void kernel_launch(void* const* d_in, const int* in_sizes, int n_in,
                              void* d_out, int out_size) {
    const int*   ids  = (const int*)d_in[0];
    const int*   am   = (const int*)d_in[1];
    const float* we   = (const float*)d_in[2];
    const float* pe   = (const float*)d_in[3];
    const float* lnes = (const float*)d_in[4];
    const float* lneb = (const float*)d_in[5];
    const float* Wq   = (const float*)d_in[6];
    const float* bq   = (const float*)d_in[7];
    const float* Wk   = (const float*)d_in[8];
    const float* bk   = (const float*)d_in[9];
    const float* Wv   = (const float*)d_in[10];
    const float* bv   = (const float*)d_in[11];
    const float* Wqg  = (const float*)d_in[12];
    const float* bqg  = (const float*)d_in[13];
    const float* Wkg  = (const float*)d_in[14];
    const float* bkg  = (const float*)d_in[15];
    const float* Wvg  = (const float*)d_in[16];
    const float* bvg  = (const float*)d_in[17];
    const float* Wo   = (const float*)d_in[18];
    const float* bo   = (const float*)d_in[19];
    const float* ln1s = (const float*)d_in[20];
    const float* ln1b = (const float*)d_in[21];
    const float* W1   = (const float*)d_in[22];
    const float* b1   = (const float*)d_in[23];
    const float* W2   = (const float*)d_in[24];
    const float* b2   = (const float*)d_in[25];
    const float* ln2s = (const float*)d_in[26];
    const float* ln2b = (const float*)d_in[27];
    const float* Wcls = (const float*)d_in[28];
    const float* bcls = (const float*)d_in[29];
    float* out = (float*)d_out;

    float *xp, *yp, *ap, *qkvp, *gkvp, *qgp, *biasp;
    __nv_bfloat16 *xbp, *hbp, *wbp;
    cudaGetSymbolAddress((void**)&xp,   g_x);
    cudaGetSymbolAddress((void**)&yp,   g_y);
    cudaGetSymbolAddress((void**)&ap,   g_attn);
    cudaGetSymbolAddress((void**)&qkvp, g_qkv);
    cudaGetSymbolAddress((void**)&gkvp, g_gkv);
    cudaGetSymbolAddress((void**)&qgp,  g_qg);
    cudaGetSymbolAddress((void**)&biasp, g_bias);
    cudaGetSymbolAddress((void**)&xbp,  g_xb);
    cudaGetSymbolAddress((void**)&hbp,  g_hb);
    cudaGetSymbolAddress((void**)&wbp,  g_wb);

    cudaFuncSetAttribute(gemm_mma_kernel, cudaFuncAttributeMaxDynamicSharedMemorySize, GSM_TOT);
    cudaFuncSetAttribute(flash_band_kernel, cudaFuncAttributeMaxDynamicSharedMemorySize, FS_TOT);

    embed_ln_kernel<<<MROWS, 256>>>(ids, we, pe, lnes, lneb, xp, xbp);

    dim3 wt_dm(CDM / 32, CDM / 32);       // (24, 24)
    dim3 wt_b(32, 8);
    size_t wseg = (size_t)CDM * 3 * CDM;  // one split matrix = 768*2304
    int actK = MROWS * CDM / 256;

    for (int l = 0; l < CL; l++) {
        size_t woff = (size_t)l * CDM * CDM;
        size_t boff = (size_t)l * CDM;
        size_t w1off = (size_t)l * CDM * CDFF;
        size_t b1off = (size_t)l * CDFF;
        size_t w2off = (size_t)l * CDFF * CDM;

        // --- fused QKV ---
        split_wt_kernel<<<wt_dm, wt_b>>>(Wq + woff, wbp,            CDM, CDM);
        split_wt_kernel<<<wt_dm, wt_b>>>(Wk + woff, wbp + wseg,     CDM, CDM);
        split_wt_kernel<<<wt_dm, wt_b>>>(Wv + woff, wbp + 2 * wseg, CDM, CDM);
        pack_bias_kernel<<<9, 256>>>(biasp, bq + boff, bk + boff, bv + boff);
        gemm_mma_kernel<<<dim3(QKV_S / 128, MROWS / 128), 256, GSM_TOT>>>(
            xbp, wbp, biasp, qkvp, nullptr, 3 * CDM, QKV_S, 0);

        flash_band_kernel<<<dim3(4, CB * CH * CNB), 256, FS_TOT>>>(qkvp, am, ap);

        // --- fused Kg/Vg + global attention ---
        qg_kernel<<<dim3(CDM / 256, CB), 256>>>(xp, Wqg + woff, bqg + boff, qgp);
        split_wt_kernel<<<wt_dm, wt_b>>>(Wkg + woff, wbp,        CDM, CDM);
        split_wt_kernel<<<wt_dm, wt_b>>>(Wvg + woff, wbp + wseg, CDM, CDM);
        pack_bias_kernel<<<6, 256>>>(biasp, bkg + boff, bvg + boff, bvg + boff);
        gemm_mma_kernel<<<dim3(GKV_S / 128, MROWS / 128), 256, GSM_TOT>>>(
            xbp, wbp, biasp, gkvp, nullptr, 3 * CDM, GKV_S, 0);
        global_attn_kernel<<<dim3(CH, CB), 256>>>(qgp, gkvp, am, ap);

        // --- Wo projection + LN1 ---
        split_act_kernel<<<actK, 256>>>(ap, xbp, CDM);
        split_wt_kernel<<<wt_dm, wt_b>>>(Wo + woff, wbp, CDM, CDM);
        gemm_mma_kernel<<<dim3(CDM / 128, MROWS / 128), 256, GSM_TOT>>>(
            xbp, wbp, bo + boff, yp, nullptr, 3 * CDM, CDM, 0);
        add_ln_kernel<<<MROWS, 256>>>(xp, yp, ln1s + boff, ln1b + boff, xbp);

        // --- FFN ---
        split_wt_kernel<<<dim3(CDFF / 32, CDM / 32), wt_b>>>(W1 + w1off, wbp, CDM, CDFF);
        gemm_mma_kernel<<<dim3(CDFF / 128, MROWS / 128), 256, GSM_TOT>>>(
            xbp, wbp, b1 + b1off, nullptr, hbp, 3 * CDM, CDFF, 2);

        split_wt_kernel<<<dim3(CDM / 32, CDFF / 32), wt_b>>>(W2 + w2off, wbp, CDFF, CDM);
        gemm_mma_kernel<<<dim3(CDM / 128, MROWS / 128), 256, GSM_TOT>>>(
            hbp, wbp, b2 + boff, yp, nullptr, 3 * CDFF, CDM, 0);
        add_ln_kernel<<<MROWS, 256>>>(xp, yp, ln2s + boff, ln2b + boff, xbp);
    }

    cls_kernel<<<4, 256>>>(xp, Wcls, bcls, out);
}